// round 8
// baseline (speedup 1.0000x reference)
#include <cuda_runtime.h>

// FNO with global head. B=16, C=16, H=W=256, L=4, modes 16x16.
// Truncated separable DFT as register-tiled fp32 GEMMs; proj2+pool commuted.
// R8: R7 + ydft grid 1024 (1 bc/block, ksplit4) + hsynth row-split x4.

#define Bn 16
#define Cn 16
#define Hn 256
#define Wn 256
#define Ln 4
#define BCHW (Bn*Cn*Hn*Wn)

__device__ float g_v0[BCHW];                 // ping
__device__ float g_v1[BCHW];                 // pong
__device__ float g_a  [Bn*Cn*Hn*32];         // x-DFT result [row][2kx+ri]
__device__ float g_vftp[4*Bn*Cn*1024];       // ydft partials [ks][bc][m*32+kx*2+ri]
__device__ float g_mix[Bn*Cn*32*32];         // after channel mix
__device__ float g_gs [Bn*Cn*Hn*32];         // h-synth [bc*256+h][kx*2+ri]
__device__ float g_etab[256*32];             // xdft E: [w][2kx+ri] = (cos, -sin)
__device__ float g_xc[16*256];               // wsynth cos[kx][w]
__device__ float g_xs[16*256];               // wsynth sin[kx][w]
__device__ float g_T [64*512];               // ydft T: [2m+ri][2h+p]
__device__ float g_E3[512*64];               // hsynth E3: [2h+ro][2m+p]
__device__ float g_pool[Bn*1024*128];        // proj partial sums

__device__ __forceinline__ float gelu_t(float x) {
    const float k0 = 0.7978845608028654f;
    const float k1 = 0.044715f;
    float y = k0 * x * (1.0f + k1 * x * x);
    float th;
    asm("tanh.approx.f32 %0, %1;" : "=f"(th) : "f"(y));
    return 0.5f * x * (1.0f + th);
}

// ---------------- build all constant tables ----------------
__global__ void k_tw() {
    int j = blockIdx.x * 256 + threadIdx.x;
    if (j < 8192) {                                   // g_etab
        int w = j >> 5, c = j & 31;
        int kx = c >> 1, ri = c & 1;
        float ang = (float)((kx * w) & 255) / 128.0f;
        g_etab[j] = ri ? -sinpif(ang) : cospif(ang);
    } else if (j < 12288) {                           // g_xc
        int e = j - 8192;
        int kx = e >> 8, w = e & 255;
        g_xc[e] = cospif((float)((kx * w) & 255) / 128.0f);
    } else if (j < 16384) {                           // g_xs
        int e = j - 12288;
        int kx = e >> 8, w = e & 255;
        g_xs[e] = sinpif((float)((kx * w) & 255) / 128.0f);
    } else if (j < 49152) {                           // g_T [2m+ri][2h+p]
        int e = j - 16384;
        int row = e >> 9, col = e & 511;
        int m = row >> 1, ri = row & 1;
        int h = col >> 1, p = col & 1;
        int ky = (m < 16) ? m : (m + 224);
        float ang = (float)((ky * h) & 255) / 128.0f;
        float cy = cospif(ang), sy = sinpif(ang);
        g_T[e] = (ri == 0) ? (p == 0 ? cy : sy) : (p == 0 ? -sy : cy);
    } else if (j < 81920) {                           // g_E3 [2h+ro][2m+p]
        int e = j - 49152;
        int row = e >> 6, col = e & 63;
        int h = row >> 1, ro = row & 1;
        int m = col >> 1, p = col & 1;
        int ky = (m < 16) ? m : (m + 224);
        float ang = (float)((ky * h) & 255) / 128.0f;
        float cy = cospif(ang), sy = sinpif(ang);
        g_E3[e] = (ro == 0) ? (p == 0 ? cy : -sy) : (p == 0 ? sy : cy);
    }
}

// ---------------- lifting 1 -> 16 channels ----------------
__global__ void k_lift(const float* __restrict__ x,
                       const float* __restrict__ lw,
                       const float* __restrict__ lb) {
    int idx = blockIdx.x * blockDim.x + threadIdx.x;
    int w = idx & 255;
    int h = (idx >> 8) & 255;
    int c = (idx >> 16) & 15;
    int b = idx >> 20;
    float xv = x[(b << 16) | (h << 8) | w];
    g_v0[idx] = lw[c] * xv + lb[c];
}

// ---------------- x-DFT GEMM: C[64 rows,32] = V[64,256] x E[256,32] ------
__global__ void __launch_bounds__(128) k_xdft(int flip) {
    __shared__ float vs[64][65];
    __shared__ float es[64][32];
    const float* __restrict__ vin = flip ? g_v1 : g_v0;
    int t = threadIdx.x;
    int rowbase = blockIdx.x * 64;
    const float* src = vin + (size_t)rowbase * 256;
    int rg = t >> 3, cg = t & 7;
    int r0 = rg * 4, c0 = cg * 4;
    float acc[4][4] = {};
    for (int wc = 0; wc < 4; wc++) {
        __syncthreads();
        for (int j = t; j < 1024; j += 128) {
            int r = j >> 4, q = j & 15;
            float4 v4 = *(const float4*)(src + r * 256 + wc * 64 + q * 4);
            vs[r][q * 4 + 0] = v4.x; vs[r][q * 4 + 1] = v4.y;
            vs[r][q * 4 + 2] = v4.z; vs[r][q * 4 + 3] = v4.w;
        }
        for (int j = t; j < 512; j += 128) {
            int k = j >> 3, q = j & 7;
            *(float4*)&es[k][q * 4] = *(const float4*)(g_etab + (wc * 64 + k) * 32 + q * 4);
        }
        __syncthreads();
        #pragma unroll 8
        for (int kk = 0; kk < 64; kk++) {
            float a0 = vs[r0 + 0][kk], a1 = vs[r0 + 1][kk];
            float a2 = vs[r0 + 2][kk], a3 = vs[r0 + 3][kk];
            float4 bf = *(const float4*)&es[kk][c0];
            acc[0][0] += a0 * bf.x; acc[0][1] += a0 * bf.y; acc[0][2] += a0 * bf.z; acc[0][3] += a0 * bf.w;
            acc[1][0] += a1 * bf.x; acc[1][1] += a1 * bf.y; acc[1][2] += a1 * bf.z; acc[1][3] += a1 * bf.w;
            acc[2][0] += a2 * bf.x; acc[2][1] += a2 * bf.y; acc[2][2] += a2 * bf.z; acc[2][3] += a2 * bf.w;
            acc[3][0] += a3 * bf.x; acc[3][1] += a3 * bf.y; acc[3][2] += a3 * bf.z; acc[3][3] += a3 * bf.w;
        }
    }
    #pragma unroll
    for (int i = 0; i < 4; i++)
        *(float4*)(g_a + (size_t)(rowbase + r0 + i) * 32 + c0) =
            make_float4(acc[i][0], acc[i][1], acc[i][2], acc[i][3]);
}

// ---------------- y-DFT GEMM, K-split x4: grid 1024 = bc*4 + ks ----------
// Each block: one bc, chunks {2ks, 2ks+1}; 128 threads; tile 4 rows x 2 kx.
__global__ void __launch_bounds__(128) k_ydft() {
    __shared__ float ts[64][65];      // [k within chunk][out row]
    __shared__ float as[64][18];      // [k within chunk][kx]
    int t = threadIdx.x;
    int ks = blockIdx.x & 3;
    int bc = blockIdx.x >> 2;
    int rg = t >> 3, cg = t & 7;
    int r0 = rg * 4, c0 = cg * 2;
    float acc[4][2] = {};
    for (int ci = 0; ci < 2; ci++) {
        int ch = ks * 2 + ci;
        int h0 = ch * 32, k0 = ch * 64;
        __syncthreads();
        for (int j = t; j < 1024; j += 128) {
            int row = j >> 4, q = j & 15;
            float4 v4 = *(const float4*)(g_T + row * 512 + k0 + q * 4);
            ts[q * 4 + 0][row] = v4.x; ts[q * 4 + 1][row] = v4.y;
            ts[q * 4 + 2][row] = v4.z; ts[q * 4 + 3][row] = v4.w;
        }
        for (int j = t; j < 256; j += 128) {
            int hh = j >> 3, q = j & 7;
            float4 v4 = *(const float4*)(g_a + (size_t)(bc * 256 + h0 + hh) * 32 + q * 4);
            as[2 * hh + 0][2 * q + 0] = v4.x;
            as[2 * hh + 1][2 * q + 0] = v4.y;
            as[2 * hh + 0][2 * q + 1] = v4.z;
            as[2 * hh + 1][2 * q + 1] = v4.w;
        }
        __syncthreads();
        #pragma unroll 8
        for (int kk = 0; kk < 64; kk++) {
            float a0 = ts[kk][r0 + 0], a1 = ts[kk][r0 + 1];
            float a2 = ts[kk][r0 + 2], a3 = ts[kk][r0 + 3];
            float2 bf = *(const float2*)&as[kk][c0];
            acc[0][0] += a0 * bf.x; acc[0][1] += a0 * bf.y;
            acc[1][0] += a1 * bf.x; acc[1][1] += a1 * bf.y;
            acc[2][0] += a2 * bf.x; acc[2][1] += a2 * bf.y;
            acc[3][0] += a3 * bf.x; acc[3][1] += a3 * bf.y;
        }
    }
    float* vout = g_vftp + (size_t)ks * (Bn * Cn * 1024);
    #pragma unroll
    for (int i = 0; i < 4; i++) {
        int r = r0 + i, m = r >> 1, ri = r & 1;
        #pragma unroll
        for (int j = 0; j < 2; j++) {
            int kx = c0 + j;
            vout[bc * 1024 + m * 32 + kx * 2 + ri] = acc[i][j];
        }
    }
}

// ---------------- per-mode 16x16 complex channel mixing (sums partials) --
__global__ void k_mix(const float* __restrict__ w1r, const float* __restrict__ w1i,
                      const float* __restrict__ w2r, const float* __restrict__ w2i,
                      int l) {
    int tid = blockIdx.x * blockDim.x + threadIdx.x;   // 131072
    int kx = tid & 15;
    int m = (tid >> 4) & 31;
    int o = (tid >> 9) & 15;
    int b = tid >> 13;
    int mm = m & 15;
    const float* wr = (m < 16) ? w1r : w2r;
    const float* wi = (m < 16) ? w1i : w2i;
    const int P = Bn * Cn * 1024;
    float accr = 0.f, acci = 0.f;
    #pragma unroll
    for (int i = 0; i < 16; i++) {
        int vidx = (b * 16 + i) * 1024 + m * 32 + kx * 2;
        float2 p0 = *(const float2*)(g_vftp + vidx);
        float2 p1 = *(const float2*)(g_vftp + P + vidx);
        float2 p2 = *(const float2*)(g_vftp + 2 * P + vidx);
        float2 p3 = *(const float2*)(g_vftp + 3 * P + vidx);
        float vr = (p0.x + p1.x) + (p2.x + p3.x);
        float vv = (p0.y + p1.y) + (p2.y + p3.y);
        int widx = (((l * 16 + i) * 16 + o) * 256) + mm * 16 + kx;
        float wrv = wr[widx], wiv = wi[widx];
        accr += vr * wrv - vv * wiv;
        acci += vr * wiv + vv * wrv;
    }
    int outi = (b * 16 + o) * 1024 + m * 32 + kx * 2;
    g_mix[outi + 0] = accr;
    g_mix[outi + 1] = acci;
}

// ---------------- h-synthesis, row-split x4: grid 1024 = bc*4 + rc -------
// Each block: rows [rc*128, rc*128+128) of C[512,16] = E3[512,64] x mixT^T.
__global__ void __launch_bounds__(256) k_hsynth() {
    __shared__ float mixT[16][68];    // [kx][2m+p]
    int t = threadIdx.x;
    int bc = blockIdx.x >> 2, rc = blockIdx.x & 3;
    {
        float4 v4 = *(const float4*)(g_mix + (size_t)bc * 1024 + t * 4);
        int i4 = t * 4;
        #pragma unroll
        for (int e = 0; e < 4; e++) {
            int idx = i4 + e;
            int m = idx >> 5, rem = idx & 31, kx = rem >> 1, p = rem & 1;
            float val = (e == 0) ? v4.x : (e == 1) ? v4.y : (e == 2) ? v4.z : v4.w;
            mixT[kx][2 * m + p] = val;
        }
    }
    __syncthreads();
    int rg = t >> 3, cg = t & 7;
    int rbase = rc * 128;
    float acc[4][2] = {};
    for (int ks = 0; ks < 64; ks += 4) {
        float4 bf0 = *(const float4*)&mixT[cg * 2 + 0][ks];
        float4 bf1 = *(const float4*)&mixT[cg * 2 + 1][ks];
        #pragma unroll
        for (int i = 0; i < 4; i++) {
            float4 af = *(const float4*)(g_E3 + (size_t)(rbase + 32 * i + rg) * 64 + ks);
            acc[i][0] += af.x * bf0.x + af.y * bf0.y + af.z * bf0.z + af.w * bf0.w;
            acc[i][1] += af.x * bf1.x + af.y * bf1.y + af.z * bf1.z + af.w * bf1.w;
        }
    }
    #pragma unroll
    for (int i = 0; i < 4; i++) {
        int r = rbase + 32 * i + rg, h = r >> 1, ro = r & 1;
        #pragma unroll
        for (int jj = 0; jj < 2; jj++) {
            int kx = cg * 2 + jj;
            float sc = (kx == 0) ? (1.0f / 65536.0f) : (2.0f / 65536.0f);
            g_gs[(size_t)(bc * 256 + h) * 32 + kx * 2 + ro] = acc[i][jj] * sc;
        }
    }
}

// ---------------- fused w-synth + skip + gelu: [16,48]x[48,256] ----------
__global__ void __launch_bounds__(256) k_wsynth(const float* __restrict__ skw,
                         const float* __restrict__ skb,
                         int l, int act, int flip) {
    __shared__ float vs[16][256];
    __shared__ float ms[16][52];      // [o][0:16 skw | 16:32 gr | 32:48 -gi]
    __shared__ float sb[16];
    const float* __restrict__ vin = flip ? g_v1 : g_v0;
    float* __restrict__ vout = flip ? g_v0 : g_v1;
    int t = threadIdx.x;
    int b = blockIdx.x >> 8, h = blockIdx.x & 255;
    for (int j = t; j < 1024; j += 256) {
        int c = j >> 6, q = j & 63;
        *(float4*)&vs[c][q * 4] =
            *(const float4*)(vin + ((size_t)(b * 16 + c) * 256 + h) * 256 + q * 4);
    }
    {
        int c = t >> 4, k = t & 15;
        ms[c][k] = skw[l * 256 + c * 16 + k];
        int base = ((size_t)(b * 16 + c) * 256 + h) * 32 + k * 2;
        ms[c][16 + k] = g_gs[base];
        ms[c][32 + k] = -g_gs[base + 1];
        if (t < 16) sb[t] = skb[l * 16 + t];
    }
    __syncthreads();
    int og = t >> 6, wg = t & 63;
    int o0 = og * 4, w0 = wg * 4;
    float acc[4][4];
    #pragma unroll
    for (int i = 0; i < 4; i++) {
        float bv = sb[o0 + i];
        acc[i][0] = bv; acc[i][1] = bv; acc[i][2] = bv; acc[i][3] = bv;
    }
    #pragma unroll
    for (int k = 0; k < 16; k++) {
        float4 bf = *(const float4*)&vs[k][w0];
        #pragma unroll
        for (int i = 0; i < 4; i++) {
            float a = ms[o0 + i][k];
            acc[i][0] += a * bf.x; acc[i][1] += a * bf.y;
            acc[i][2] += a * bf.z; acc[i][3] += a * bf.w;
        }
    }
    #pragma unroll
    for (int kx = 0; kx < 16; kx++) {
        float4 bf = *(const float4*)(g_xc + kx * 256 + w0);
        #pragma unroll
        for (int i = 0; i < 4; i++) {
            float a = ms[o0 + i][16 + kx];
            acc[i][0] += a * bf.x; acc[i][1] += a * bf.y;
            acc[i][2] += a * bf.z; acc[i][3] += a * bf.w;
        }
    }
    #pragma unroll
    for (int kx = 0; kx < 16; kx++) {
        float4 bf = *(const float4*)(g_xs + kx * 256 + w0);
        #pragma unroll
        for (int i = 0; i < 4; i++) {
            float a = ms[o0 + i][32 + kx];
            acc[i][0] += a * bf.x; acc[i][1] += a * bf.y;
            acc[i][2] += a * bf.z; acc[i][3] += a * bf.w;
        }
    }
    #pragma unroll
    for (int i = 0; i < 4; i++) {
        float4 r;
        if (act) {
            r.x = gelu_t(acc[i][0]); r.y = gelu_t(acc[i][1]);
            r.z = gelu_t(acc[i][2]); r.w = gelu_t(acc[i][3]);
        } else {
            r.x = acc[i][0]; r.y = acc[i][1]; r.z = acc[i][2]; r.w = acc[i][3];
        }
        *(float4*)(vout + ((size_t)(b * 16 + o0 + i) * 256 + h) * 256 + w0) = r;
    }
}

// ---------------- proj1 (16->128) + gelu + partial pooling ----------------
__global__ void __launch_bounds__(128) k_proj(const float* __restrict__ w1,
                                              const float* __restrict__ b1) {
    __shared__ float4 vs4[16][16];
    __shared__ float red[4][128];
    int t = threadIdx.x;
    int blk = blockIdx.x;                 // b*1024 + h*4 + wc
    int wc = blk & 3, h = (blk >> 2) & 255, b = blk >> 10;
    const float* vrow = g_v0 + ((size_t)(b * 16) * 256 + h) * 256 + wc * 64;
    for (int j = t; j < 256; j += 128) {
        int i = j >> 4, p4 = j & 15;
        vs4[i][p4] = ((const float4*)(vrow + (size_t)i * 65536))[p4];
    }
    __syncthreads();
    int oc = t & 31, psub = t >> 5;
    int o0 = oc * 4;
    float wreg[4][16];
    #pragma unroll
    for (int j = 0; j < 4; j++)
        #pragma unroll
        for (int i = 0; i < 16; i++)
            wreg[j][i] = w1[(o0 + j) * 16 + i];
    float bb[4];
    #pragma unroll
    for (int j = 0; j < 4; j++) bb[j] = b1[o0 + j];
    float acc[4] = {0, 0, 0, 0};
    #pragma unroll
    for (int pg = 0; pg < 4; pg++) {
        float4 s[4];
        #pragma unroll
        for (int j = 0; j < 4; j++) s[j] = make_float4(bb[j], bb[j], bb[j], bb[j]);
        #pragma unroll
        for (int i = 0; i < 16; i++) {
            float4 v = vs4[i][psub * 4 + pg];
            #pragma unroll
            for (int j = 0; j < 4; j++) {
                s[j].x += wreg[j][i] * v.x;
                s[j].y += wreg[j][i] * v.y;
                s[j].z += wreg[j][i] * v.z;
                s[j].w += wreg[j][i] * v.w;
            }
        }
        #pragma unroll
        for (int j = 0; j < 4; j++)
            acc[j] += gelu_t(s[j].x) + gelu_t(s[j].y) + gelu_t(s[j].z) + gelu_t(s[j].w);
    }
    #pragma unroll
    for (int j = 0; j < 4; j++) red[psub][o0 + j] = acc[j];
    __syncthreads();
    if (t < 128) {
        float s = red[0][t] + red[1][t] + red[2][t] + red[3][t];
        g_pool[(size_t)blk * 128 + t] = s;
    }
}

// ---------------- final reduce + proj2 on pooled vector + head -----------
__global__ void k_head(const float* __restrict__ w2, const float* __restrict__ b2,
                       const float* __restrict__ hw_, const float* __restrict__ hb,
                       float* __restrict__ out) {
    __shared__ float pq[128];
    __shared__ float f[64];
    int b = blockIdx.x, t = threadIdx.x;
    float s = 0.f;
    for (int k = 0; k < 1024; k++)
        s += g_pool[((size_t)(b * 1024 + k)) * 128 + t];
    pq[t] = s * (1.0f / 65536.0f);
    __syncthreads();
    if (t < 64) {
        float a = b2[t];
        #pragma unroll 8
        for (int i = 0; i < 128; i++) a += w2[t * 128 + i] * pq[i];
        f[t] = a;
    }
    __syncthreads();
    if (t < 2) {
        float a = hb[t];
        #pragma unroll
        for (int o = 0; o < 64; o++) a += hw_[t * 64 + o] * f[o];
        float e = __expf(2.0f * a);
        out[b * 2 + t] = 1.0f - 2.0f / (e + 1.0f);
    }
}

extern "C" void kernel_launch(void* const* d_in, const int* in_sizes, int n_in,
                              void* d_out, int out_size) {
    const float* x    = (const float*)d_in[0];
    const float* lw   = (const float*)d_in[1];
    const float* lb   = (const float*)d_in[2];
    const float* w1r  = (const float*)d_in[3];
    const float* w1i  = (const float*)d_in[4];
    const float* w2r  = (const float*)d_in[5];
    const float* w2i  = (const float*)d_in[6];
    const float* skw  = (const float*)d_in[7];
    const float* skb  = (const float*)d_in[8];
    const float* pw1  = (const float*)d_in[9];
    const float* pb1  = (const float*)d_in[10];
    const float* pw2  = (const float*)d_in[11];
    const float* pb2  = (const float*)d_in[12];
    const float* hw_  = (const float*)d_in[13];
    const float* hb   = (const float*)d_in[14];
    float* out = (float*)d_out;

    k_tw<<<320, 256>>>();
    k_lift<<<BCHW / 256, 256>>>(x, lw, lb);
    for (int l = 0; l < Ln; l++) {
        int flip = l & 1;                    // input buffer: 0 -> g_v0
        k_xdft  <<<1024, 128>>>(flip);
        k_ydft  <<<1024, 128>>>();
        k_mix   <<<512, 256>>>(w1r, w1i, w2r, w2i, l);
        k_hsynth<<<1024, 256>>>();
        k_wsynth<<<4096, 256>>>(skw, skb, l, (l < Ln - 1) ? 1 : 0, flip);
    }
    // after 4 layers result is in g_v0
    k_proj<<<16384, 128>>>(pw1, pb1);
    k_head<<<Bn, 128>>>(pw2, pb2, hw_, hb, out);
}

// round 9
// speedup vs baseline: 1.7327x; 1.7327x over previous
#include <cuda_runtime.h>

// FNO with global head. B=16, C=16, H=W=256, L=4, modes 16x16.
// Truncated separable DFT as register-tiled fp32 GEMMs; proj2+pool commuted.
// R9: R7 base (best=1129) + k_proj converted to tf32 mma.sync tensor-core GEMM.

#define Bn 16
#define Cn 16
#define Hn 256
#define Wn 256
#define Ln 4
#define BCHW (Bn*Cn*Hn*Wn)

__device__ float g_v0[BCHW];                 // ping
__device__ float g_v1[BCHW];                 // pong
__device__ float g_a  [Bn*Cn*Hn*32];         // x-DFT result [row][2kx+ri]
__device__ float g_vftp[4*Bn*Cn*1024];       // ydft partials [ks][bc][m*32+kx*2+ri]
__device__ float g_mix[Bn*Cn*32*32];         // after channel mix
__device__ float g_gs [Bn*Cn*Hn*32];         // h-synth [bc*256+h][kx*2+ri]
__device__ float g_etab[256*32];             // xdft E: [w][2kx+ri] = (cos, -sin)
__device__ float g_xc[16*256];               // wsynth cos[kx][w]
__device__ float g_xs[16*256];               // wsynth sin[kx][w]
__device__ float g_T [64*512];               // ydft T: [2m+ri][2h+p]
__device__ float g_E3[512*64];               // hsynth E3: [2h+ro][2m+p]
__device__ float g_pool[Bn*1024*128];        // proj partial sums

__device__ __forceinline__ float gelu_t(float x) {
    const float k0 = 0.7978845608028654f;
    const float k1 = 0.044715f;
    float y = k0 * x * (1.0f + k1 * x * x);
    float th;
    asm("tanh.approx.f32 %0, %1;" : "=f"(th) : "f"(y));
    return 0.5f * x * (1.0f + th);
}

__device__ __forceinline__ unsigned f2tf32(float f) {
    unsigned u;
    asm("cvt.rna.tf32.f32 %0, %1;" : "=r"(u) : "f"(f));
    return u;
}

// ---------------- build all constant tables ----------------
__global__ void k_tw() {
    int j = blockIdx.x * 256 + threadIdx.x;
    if (j < 8192) {                                   // g_etab
        int w = j >> 5, c = j & 31;
        int kx = c >> 1, ri = c & 1;
        float ang = (float)((kx * w) & 255) / 128.0f;
        g_etab[j] = ri ? -sinpif(ang) : cospif(ang);
    } else if (j < 12288) {                           // g_xc
        int e = j - 8192;
        int kx = e >> 8, w = e & 255;
        g_xc[e] = cospif((float)((kx * w) & 255) / 128.0f);
    } else if (j < 16384) {                           // g_xs
        int e = j - 12288;
        int kx = e >> 8, w = e & 255;
        g_xs[e] = sinpif((float)((kx * w) & 255) / 128.0f);
    } else if (j < 49152) {                           // g_T [2m+ri][2h+p]
        int e = j - 16384;
        int row = e >> 9, col = e & 511;
        int m = row >> 1, ri = row & 1;
        int h = col >> 1, p = col & 1;
        int ky = (m < 16) ? m : (m + 224);
        float ang = (float)((ky * h) & 255) / 128.0f;
        float cy = cospif(ang), sy = sinpif(ang);
        g_T[e] = (ri == 0) ? (p == 0 ? cy : sy) : (p == 0 ? -sy : cy);
    } else if (j < 81920) {                           // g_E3 [2h+ro][2m+p]
        int e = j - 49152;
        int row = e >> 6, col = e & 63;
        int h = row >> 1, ro = row & 1;
        int m = col >> 1, p = col & 1;
        int ky = (m < 16) ? m : (m + 224);
        float ang = (float)((ky * h) & 255) / 128.0f;
        float cy = cospif(ang), sy = sinpif(ang);
        g_E3[e] = (ro == 0) ? (p == 0 ? cy : -sy) : (p == 0 ? sy : cy);
    }
}

// ---------------- lifting 1 -> 16 channels ----------------
__global__ void k_lift(const float* __restrict__ x,
                       const float* __restrict__ lw,
                       const float* __restrict__ lb) {
    int idx = blockIdx.x * blockDim.x + threadIdx.x;
    int w = idx & 255;
    int h = (idx >> 8) & 255;
    int c = (idx >> 16) & 15;
    int b = idx >> 20;
    float xv = x[(b << 16) | (h << 8) | w];
    g_v0[idx] = lw[c] * xv + lb[c];
}

// ---------------- x-DFT GEMM: C[64 rows,32] = V[64,256] x E[256,32] ------
__global__ void __launch_bounds__(128) k_xdft(int flip) {
    __shared__ float vs[64][65];
    __shared__ float es[64][32];
    const float* __restrict__ vin = flip ? g_v1 : g_v0;
    int t = threadIdx.x;
    int rowbase = blockIdx.x * 64;
    const float* src = vin + (size_t)rowbase * 256;
    int rg = t >> 3, cg = t & 7;
    int r0 = rg * 4, c0 = cg * 4;
    float acc[4][4] = {};
    for (int wc = 0; wc < 4; wc++) {
        __syncthreads();
        for (int j = t; j < 1024; j += 128) {
            int r = j >> 4, q = j & 15;
            float4 v4 = *(const float4*)(src + r * 256 + wc * 64 + q * 4);
            vs[r][q * 4 + 0] = v4.x; vs[r][q * 4 + 1] = v4.y;
            vs[r][q * 4 + 2] = v4.z; vs[r][q * 4 + 3] = v4.w;
        }
        for (int j = t; j < 512; j += 128) {
            int k = j >> 3, q = j & 7;
            *(float4*)&es[k][q * 4] = *(const float4*)(g_etab + (wc * 64 + k) * 32 + q * 4);
        }
        __syncthreads();
        #pragma unroll 8
        for (int kk = 0; kk < 64; kk++) {
            float a0 = vs[r0 + 0][kk], a1 = vs[r0 + 1][kk];
            float a2 = vs[r0 + 2][kk], a3 = vs[r0 + 3][kk];
            float4 bf = *(const float4*)&es[kk][c0];
            acc[0][0] += a0 * bf.x; acc[0][1] += a0 * bf.y; acc[0][2] += a0 * bf.z; acc[0][3] += a0 * bf.w;
            acc[1][0] += a1 * bf.x; acc[1][1] += a1 * bf.y; acc[1][2] += a1 * bf.z; acc[1][3] += a1 * bf.w;
            acc[2][0] += a2 * bf.x; acc[2][1] += a2 * bf.y; acc[2][2] += a2 * bf.z; acc[2][3] += a2 * bf.w;
            acc[3][0] += a3 * bf.x; acc[3][1] += a3 * bf.y; acc[3][2] += a3 * bf.z; acc[3][3] += a3 * bf.w;
        }
    }
    #pragma unroll
    for (int i = 0; i < 4; i++)
        *(float4*)(g_a + (size_t)(rowbase + r0 + i) * 32 + c0) =
            make_float4(acc[i][0], acc[i][1], acc[i][2], acc[i][3]);
}

// ---------------- y-DFT GEMM, K-split x4: per (2bc, ks): partial C --------
// grid 512 = (bc/2) * 4 ksplits; 128 threads; tile 4x4.
__global__ void __launch_bounds__(128) k_ydft() {
    __shared__ float ts[64][65];      // [k within chunk][out row]
    __shared__ float as[64][36];      // [k within chunk][col = bcq*16+kx]
    int t = threadIdx.x;
    int ks = blockIdx.x & 3;
    int bc0 = (blockIdx.x >> 2) * 2;
    int rg = t >> 3, cg = t & 7;
    int r0 = rg * 4, c0 = cg * 4;
    float acc[4][4] = {};
    for (int ci = 0; ci < 2; ci++) {
        int ch = ks * 2 + ci;
        int h0 = ch * 32, k0 = ch * 64;
        __syncthreads();
        for (int j = t; j < 1024; j += 128) {
            int row = j >> 4, q = j & 15;
            float4 v4 = *(const float4*)(g_T + row * 512 + k0 + q * 4);
            ts[q * 4 + 0][row] = v4.x; ts[q * 4 + 1][row] = v4.y;
            ts[q * 4 + 2][row] = v4.z; ts[q * 4 + 3][row] = v4.w;
        }
        for (int j = t; j < 512; j += 128) {
            int bcq = j >> 8, rem = j & 255, hh = rem >> 3, q = rem & 7;
            float4 v4 = *(const float4*)(g_a + (size_t)((bc0 + bcq) * 256 + h0 + hh) * 32 + q * 4);
            int n0 = bcq * 16 + q * 2;
            as[2 * hh + 0][n0] = v4.x;     as[2 * hh + 1][n0] = v4.y;
            as[2 * hh + 0][n0 + 1] = v4.z; as[2 * hh + 1][n0 + 1] = v4.w;
        }
        __syncthreads();
        #pragma unroll 8
        for (int kk = 0; kk < 64; kk++) {
            float a0 = ts[kk][r0 + 0], a1 = ts[kk][r0 + 1];
            float a2 = ts[kk][r0 + 2], a3 = ts[kk][r0 + 3];
            float4 bf = *(const float4*)&as[kk][c0];
            acc[0][0] += a0 * bf.x; acc[0][1] += a0 * bf.y; acc[0][2] += a0 * bf.z; acc[0][3] += a0 * bf.w;
            acc[1][0] += a1 * bf.x; acc[1][1] += a1 * bf.y; acc[1][2] += a1 * bf.z; acc[1][3] += a1 * bf.w;
            acc[2][0] += a2 * bf.x; acc[2][1] += a2 * bf.y; acc[2][2] += a2 * bf.z; acc[2][3] += a2 * bf.w;
            acc[3][0] += a3 * bf.x; acc[3][1] += a3 * bf.y; acc[3][2] += a3 * bf.z; acc[3][3] += a3 * bf.w;
        }
    }
    float* vout = g_vftp + (size_t)ks * (Bn * Cn * 1024);
    #pragma unroll
    for (int i = 0; i < 4; i++) {
        int r = r0 + i, m = r >> 1, ri = r & 1;
        #pragma unroll
        for (int j = 0; j < 4; j++) {
            int c = c0 + j, bcq = c >> 4, kx = c & 15;
            vout[(bc0 + bcq) * 1024 + m * 32 + kx * 2 + ri] = acc[i][j];
        }
    }
}

// ---------------- per-mode 16x16 complex channel mixing (sums partials) --
__global__ void k_mix(const float* __restrict__ w1r, const float* __restrict__ w1i,
                      const float* __restrict__ w2r, const float* __restrict__ w2i,
                      int l) {
    int tid = blockIdx.x * blockDim.x + threadIdx.x;   // 131072
    int kx = tid & 15;
    int m = (tid >> 4) & 31;
    int o = (tid >> 9) & 15;
    int b = tid >> 13;
    int mm = m & 15;
    const float* wr = (m < 16) ? w1r : w2r;
    const float* wi = (m < 16) ? w1i : w2i;
    const int P = Bn * Cn * 1024;
    float accr = 0.f, acci = 0.f;
    #pragma unroll
    for (int i = 0; i < 16; i++) {
        int vidx = (b * 16 + i) * 1024 + m * 32 + kx * 2;
        float2 p0 = *(const float2*)(g_vftp + vidx);
        float2 p1 = *(const float2*)(g_vftp + P + vidx);
        float2 p2 = *(const float2*)(g_vftp + 2 * P + vidx);
        float2 p3 = *(const float2*)(g_vftp + 3 * P + vidx);
        float vr = (p0.x + p1.x) + (p2.x + p3.x);
        float vv = (p0.y + p1.y) + (p2.y + p3.y);
        int widx = (((l * 16 + i) * 16 + o) * 256) + mm * 16 + kx;
        float wrv = wr[widx], wiv = wi[widx];
        accr += vr * wrv - vv * wiv;
        acci += vr * wiv + vv * wrv;
    }
    int outi = (b * 16 + o) * 1024 + m * 32 + kx * 2;
    g_mix[outi + 0] = accr;
    g_mix[outi + 1] = acci;
}

// ---------------- h-synthesis GEMM per bc: C[512,16] = E3[512,64] x M ----
__global__ void __launch_bounds__(256) k_hsynth() {
    __shared__ float mixT[16][68];    // [kx][2m+p]
    int t = threadIdx.x;
    int bc = blockIdx.x;
    {
        float4 v4 = *(const float4*)(g_mix + (size_t)bc * 1024 + t * 4);
        int i4 = t * 4;
        #pragma unroll
        for (int e = 0; e < 4; e++) {
            int idx = i4 + e;
            int m = idx >> 5, rem = idx & 31, kx = rem >> 1, p = rem & 1;
            float val = (e == 0) ? v4.x : (e == 1) ? v4.y : (e == 2) ? v4.z : v4.w;
            mixT[kx][2 * m + p] = val;
        }
    }
    __syncthreads();
    int rg = t >> 3, cg = t & 7;
    float acc[16][2] = {};
    for (int ks = 0; ks < 64; ks += 4) {
        float4 bf0 = *(const float4*)&mixT[cg * 2 + 0][ks];
        float4 bf1 = *(const float4*)&mixT[cg * 2 + 1][ks];
        #pragma unroll
        for (int i = 0; i < 16; i++) {
            float4 af = *(const float4*)(g_E3 + (size_t)(32 * i + rg) * 64 + ks);
            acc[i][0] += af.x * bf0.x + af.y * bf0.y + af.z * bf0.z + af.w * bf0.w;
            acc[i][1] += af.x * bf1.x + af.y * bf1.y + af.z * bf1.z + af.w * bf1.w;
        }
    }
    #pragma unroll
    for (int i = 0; i < 16; i++) {
        int r = 32 * i + rg, h = r >> 1, ro = r & 1;
        #pragma unroll
        for (int jj = 0; jj < 2; jj++) {
            int kx = cg * 2 + jj;
            float sc = (kx == 0) ? (1.0f / 65536.0f) : (2.0f / 65536.0f);
            g_gs[(size_t)(bc * 256 + h) * 32 + kx * 2 + ro] = acc[i][jj] * sc;
        }
    }
}

// ---------------- fused w-synth + skip + gelu: [16,48]x[48,256] ----------
__global__ void __launch_bounds__(256) k_wsynth(const float* __restrict__ skw,
                         const float* __restrict__ skb,
                         int l, int act, int flip) {
    __shared__ float vs[16][256];
    __shared__ float ms[16][52];      // [o][0:16 skw | 16:32 gr | 32:48 -gi]
    __shared__ float sb[16];
    const float* __restrict__ vin = flip ? g_v1 : g_v0;
    float* __restrict__ vout = flip ? g_v0 : g_v1;
    int t = threadIdx.x;
    int b = blockIdx.x >> 8, h = blockIdx.x & 255;
    for (int j = t; j < 1024; j += 256) {
        int c = j >> 6, q = j & 63;
        *(float4*)&vs[c][q * 4] =
            *(const float4*)(vin + ((size_t)(b * 16 + c) * 256 + h) * 256 + q * 4);
    }
    {
        int c = t >> 4, k = t & 15;
        ms[c][k] = skw[l * 256 + c * 16 + k];
        int base = ((size_t)(b * 16 + c) * 256 + h) * 32 + k * 2;
        ms[c][16 + k] = g_gs[base];
        ms[c][32 + k] = -g_gs[base + 1];
        if (t < 16) sb[t] = skb[l * 16 + t];
    }
    __syncthreads();
    int og = t >> 6, wg = t & 63;
    int o0 = og * 4, w0 = wg * 4;
    float acc[4][4];
    #pragma unroll
    for (int i = 0; i < 4; i++) {
        float bv = sb[o0 + i];
        acc[i][0] = bv; acc[i][1] = bv; acc[i][2] = bv; acc[i][3] = bv;
    }
    #pragma unroll
    for (int k = 0; k < 16; k++) {
        float4 bf = *(const float4*)&vs[k][w0];
        #pragma unroll
        for (int i = 0; i < 4; i++) {
            float a = ms[o0 + i][k];
            acc[i][0] += a * bf.x; acc[i][1] += a * bf.y;
            acc[i][2] += a * bf.z; acc[i][3] += a * bf.w;
        }
    }
    #pragma unroll
    for (int kx = 0; kx < 16; kx++) {
        float4 bf = *(const float4*)(g_xc + kx * 256 + w0);
        #pragma unroll
        for (int i = 0; i < 4; i++) {
            float a = ms[o0 + i][16 + kx];
            acc[i][0] += a * bf.x; acc[i][1] += a * bf.y;
            acc[i][2] += a * bf.z; acc[i][3] += a * bf.w;
        }
    }
    #pragma unroll
    for (int kx = 0; kx < 16; kx++) {
        float4 bf = *(const float4*)(g_xs + kx * 256 + w0);
        #pragma unroll
        for (int i = 0; i < 4; i++) {
            float a = ms[o0 + i][32 + kx];
            acc[i][0] += a * bf.x; acc[i][1] += a * bf.y;
            acc[i][2] += a * bf.z; acc[i][3] += a * bf.w;
        }
    }
    #pragma unroll
    for (int i = 0; i < 4; i++) {
        float4 r;
        if (act) {
            r.x = gelu_t(acc[i][0]); r.y = gelu_t(acc[i][1]);
            r.z = gelu_t(acc[i][2]); r.w = gelu_t(acc[i][3]);
        } else {
            r.x = acc[i][0]; r.y = acc[i][1]; r.z = acc[i][2]; r.w = acc[i][3];
        }
        *(float4*)(vout + ((size_t)(b * 16 + o0 + i) * 256 + h) * 256 + w0) = r;
    }
}

// ---------------- proj1 (16->128) + gelu + pooling via tf32 mma.sync -----
// Block = (b, h, 64-pixel chunk); 128 thr = 4 warps; warp -> 32 out channels.
// D[128,64] = W1[128,16] x V[16,64]; m16n8k8: 2 m-tiles x 8 n-tiles x 2 k.
__global__ void __launch_bounds__(128) k_proj(const float* __restrict__ w1,
                                              const float* __restrict__ b1) {
    __shared__ float vs[16][72];          // stride 72: conflict-free B reads
    int t = threadIdx.x;
    int lane = t & 31, warp = t >> 5;
    int blk = blockIdx.x;                 // b*1024 + h*4 + wc
    int wc = blk & 3, h = (blk >> 2) & 255, b = blk >> 10;
    const float* vrow = g_v0 + ((size_t)(b * 16) * 256 + h) * 256 + wc * 64;
    for (int j = t; j < 256; j += 128) {  // 256 float4 = 16ch x 64px
        int c = j >> 4, p4 = j & 15;
        float4 v4 = ((const float4*)(vrow + (size_t)c * 65536))[p4];
        vs[c][p4 * 4 + 0] = v4.x; vs[c][p4 * 4 + 1] = v4.y;
        vs[c][p4 * 4 + 2] = v4.z; vs[c][p4 * 4 + 3] = v4.w;
    }
    int gid = lane >> 2, tig = lane & 3;  // groupID, threadID_in_group
    int m_base = warp * 32;
    // A fragments (row-major W1[oc][k]) and biases
    unsigned a[2][2][4];
    float bb[2][2];
    #pragma unroll
    for (int mt = 0; mt < 2; mt++) {
        int r_lo = m_base + mt * 16 + gid;
        bb[mt][0] = b1[r_lo];
        bb[mt][1] = b1[r_lo + 8];
        #pragma unroll
        for (int ks = 0; ks < 2; ks++) {
            int c_lo = ks * 8 + tig;
            a[mt][ks][0] = f2tf32(w1[r_lo * 16 + c_lo]);
            a[mt][ks][1] = f2tf32(w1[(r_lo + 8) * 16 + c_lo]);
            a[mt][ks][2] = f2tf32(w1[r_lo * 16 + c_lo + 4]);
            a[mt][ks][3] = f2tf32(w1[(r_lo + 8) * 16 + c_lo + 4]);
        }
    }
    __syncthreads();
    float s[2][2] = {};                    // pooled sums per (mt, row-half)
    #pragma unroll
    for (int nt = 0; nt < 8; nt++) {
        int n = nt * 8 + gid;
        unsigned bfr[2][2];
        #pragma unroll
        for (int ks = 0; ks < 2; ks++) {
            bfr[ks][0] = f2tf32(vs[ks * 8 + tig][n]);
            bfr[ks][1] = f2tf32(vs[ks * 8 + tig + 4][n]);
        }
        #pragma unroll
        for (int mt = 0; mt < 2; mt++) {
            float d0 = 0.f, d1 = 0.f, d2 = 0.f, d3 = 0.f;
            #pragma unroll
            for (int ks = 0; ks < 2; ks++) {
                asm volatile(
                    "mma.sync.aligned.m16n8k8.row.col.f32.tf32.tf32.f32 "
                    "{%0,%1,%2,%3}, {%4,%5,%6,%7}, {%8,%9}, {%0,%1,%2,%3};\n"
                    : "+f"(d0), "+f"(d1), "+f"(d2), "+f"(d3)
                    : "r"(a[mt][ks][0]), "r"(a[mt][ks][1]),
                      "r"(a[mt][ks][2]), "r"(a[mt][ks][3]),
                      "r"(bfr[ks][0]), "r"(bfr[ks][1]));
            }
            s[mt][0] += gelu_t(d0 + bb[mt][0]) + gelu_t(d1 + bb[mt][0]);
            s[mt][1] += gelu_t(d2 + bb[mt][1]) + gelu_t(d3 + bb[mt][1]);
        }
    }
    // reduce across the quad (cols 2*tig, 2*tig+1 over tig=0..3 = all 8 cols)
    #pragma unroll
    for (int mt = 0; mt < 2; mt++) {
        #pragma unroll
        for (int hh = 0; hh < 2; hh++) {
            float v = s[mt][hh];
            v += __shfl_xor_sync(0xFFFFFFFFu, v, 1);
            v += __shfl_xor_sync(0xFFFFFFFFu, v, 2);
            s[mt][hh] = v;
        }
    }
    if (tig == 0) {
        float* dst = g_pool + (size_t)blk * 128;
        #pragma unroll
        for (int mt = 0; mt < 2; mt++) {
            dst[m_base + mt * 16 + gid]     = s[mt][0];
            dst[m_base + mt * 16 + gid + 8] = s[mt][1];
        }
    }
}

// ---------------- final reduce + proj2 on pooled vector + head -----------
__global__ void k_head(const float* __restrict__ w2, const float* __restrict__ b2,
                       const float* __restrict__ hw_, const float* __restrict__ hb,
                       float* __restrict__ out) {
    __shared__ float pq[128];
    __shared__ float f[64];
    int b = blockIdx.x, t = threadIdx.x;
    float s = 0.f;
    for (int k = 0; k < 1024; k++)
        s += g_pool[((size_t)(b * 1024 + k)) * 128 + t];
    pq[t] = s * (1.0f / 65536.0f);
    __syncthreads();
    if (t < 64) {
        float a = b2[t];
        #pragma unroll 8
        for (int i = 0; i < 128; i++) a += w2[t * 128 + i] * pq[i];
        f[t] = a;
    }
    __syncthreads();
    if (t < 2) {
        float a = hb[t];
        #pragma unroll
        for (int o = 0; o < 64; o++) a += hw_[t * 64 + o] * f[o];
        float e = __expf(2.0f * a);
        out[b * 2 + t] = 1.0f - 2.0f / (e + 1.0f);
    }
}

extern "C" void kernel_launch(void* const* d_in, const int* in_sizes, int n_in,
                              void* d_out, int out_size) {
    const float* x    = (const float*)d_in[0];
    const float* lw   = (const float*)d_in[1];
    const float* lb   = (const float*)d_in[2];
    const float* w1r  = (const float*)d_in[3];
    const float* w1i  = (const float*)d_in[4];
    const float* w2r  = (const float*)d_in[5];
    const float* w2i  = (const float*)d_in[6];
    const float* skw  = (const float*)d_in[7];
    const float* skb  = (const float*)d_in[8];
    const float* pw1  = (const float*)d_in[9];
    const float* pb1  = (const float*)d_in[10];
    const float* pw2  = (const float*)d_in[11];
    const float* pb2  = (const float*)d_in[12];
    const float* hw_  = (const float*)d_in[13];
    const float* hb   = (const float*)d_in[14];
    float* out = (float*)d_out;

    k_tw<<<320, 256>>>();
    k_lift<<<BCHW / 256, 256>>>(x, lw, lb);
    for (int l = 0; l < Ln; l++) {
        int flip = l & 1;                    // input buffer: 0 -> g_v0
        k_xdft  <<<1024, 128>>>(flip);
        k_ydft  <<<512, 128>>>();
        k_mix   <<<512, 256>>>(w1r, w1i, w2r, w2i, l);
        k_hsynth<<<256, 256>>>();
        k_wsynth<<<4096, 256>>>(skw, skb, l, (l < Ln - 1) ? 1 : 0, flip);
    }
    // after 4 layers result is in g_v0
    k_proj<<<16384, 128>>>(pw1, pb1);
    k_head<<<Bn, 128>>>(pw2, pb2, hw_, hb, out);
}

// round 10
// speedup vs baseline: 1.8883x; 1.0898x over previous
#include <cuda_runtime.h>

// FNO with global head. B=16, C=16, H=W=256, L=4, modes 16x16.
// Truncated separable DFT as register-tiled fp32 GEMMs; proj2+pool commuted.
// R10: R9 base (665us) + k_wsynth converted to tf32 mma.sync.

#define Bn 16
#define Cn 16
#define Hn 256
#define Wn 256
#define Ln 4
#define BCHW (Bn*Cn*Hn*Wn)

__device__ float g_v0[BCHW];                 // ping
__device__ float g_v1[BCHW];                 // pong
__device__ float g_a  [Bn*Cn*Hn*32];         // x-DFT result [row][2kx+ri]
__device__ float g_vftp[4*Bn*Cn*1024];       // ydft partials [ks][bc][m*32+kx*2+ri]
__device__ float g_mix[Bn*Cn*32*32];         // after channel mix
__device__ float g_gs [Bn*Cn*Hn*32];         // h-synth [bc*256+h][kx*2+ri]
__device__ float g_etab[256*32];             // xdft E: [w][2kx+ri] = (cos, -sin)
__device__ float g_xc[16*256];               // wsynth cos[kx][w]
__device__ float g_xs[16*256];               // wsynth sin[kx][w]
__device__ float g_T [64*512];               // ydft T: [2m+ri][2h+p]
__device__ float g_E3[512*64];               // hsynth E3: [2h+ro][2m+p]
__device__ float g_pool[Bn*1024*128];        // proj partial sums

__device__ __forceinline__ float gelu_t(float x) {
    const float k0 = 0.7978845608028654f;
    const float k1 = 0.044715f;
    float y = k0 * x * (1.0f + k1 * x * x);
    float th;
    asm("tanh.approx.f32 %0, %1;" : "=f"(th) : "f"(y));
    return 0.5f * x * (1.0f + th);
}

__device__ __forceinline__ unsigned f2tf32(float f) {
    unsigned u;
    asm("cvt.rna.tf32.f32 %0, %1;" : "=r"(u) : "f"(f));
    return u;
}

// ---------------- build all constant tables ----------------
__global__ void k_tw() {
    int j = blockIdx.x * 256 + threadIdx.x;
    if (j < 8192) {                                   // g_etab
        int w = j >> 5, c = j & 31;
        int kx = c >> 1, ri = c & 1;
        float ang = (float)((kx * w) & 255) / 128.0f;
        g_etab[j] = ri ? -sinpif(ang) : cospif(ang);
    } else if (j < 12288) {                           // g_xc
        int e = j - 8192;
        int kx = e >> 8, w = e & 255;
        g_xc[e] = cospif((float)((kx * w) & 255) / 128.0f);
    } else if (j < 16384) {                           // g_xs
        int e = j - 12288;
        int kx = e >> 8, w = e & 255;
        g_xs[e] = sinpif((float)((kx * w) & 255) / 128.0f);
    } else if (j < 49152) {                           // g_T [2m+ri][2h+p]
        int e = j - 16384;
        int row = e >> 9, col = e & 511;
        int m = row >> 1, ri = row & 1;
        int h = col >> 1, p = col & 1;
        int ky = (m < 16) ? m : (m + 224);
        float ang = (float)((ky * h) & 255) / 128.0f;
        float cy = cospif(ang), sy = sinpif(ang);
        g_T[e] = (ri == 0) ? (p == 0 ? cy : sy) : (p == 0 ? -sy : cy);
    } else if (j < 81920) {                           // g_E3 [2h+ro][2m+p]
        int e = j - 49152;
        int row = e >> 6, col = e & 63;
        int h = row >> 1, ro = row & 1;
        int m = col >> 1, p = col & 1;
        int ky = (m < 16) ? m : (m + 224);
        float ang = (float)((ky * h) & 255) / 128.0f;
        float cy = cospif(ang), sy = sinpif(ang);
        g_E3[e] = (ro == 0) ? (p == 0 ? cy : -sy) : (p == 0 ? sy : cy);
    }
}

// ---------------- lifting 1 -> 16 channels ----------------
__global__ void k_lift(const float* __restrict__ x,
                       const float* __restrict__ lw,
                       const float* __restrict__ lb) {
    int idx = blockIdx.x * blockDim.x + threadIdx.x;
    int w = idx & 255;
    int h = (idx >> 8) & 255;
    int c = (idx >> 16) & 15;
    int b = idx >> 20;
    float xv = x[(b << 16) | (h << 8) | w];
    g_v0[idx] = lw[c] * xv + lb[c];
}

// ---------------- x-DFT GEMM: C[64 rows,32] = V[64,256] x E[256,32] ------
__global__ void __launch_bounds__(128) k_xdft(int flip) {
    __shared__ float vs[64][65];
    __shared__ float es[64][32];
    const float* __restrict__ vin = flip ? g_v1 : g_v0;
    int t = threadIdx.x;
    int rowbase = blockIdx.x * 64;
    const float* src = vin + (size_t)rowbase * 256;
    int rg = t >> 3, cg = t & 7;
    int r0 = rg * 4, c0 = cg * 4;
    float acc[4][4] = {};
    for (int wc = 0; wc < 4; wc++) {
        __syncthreads();
        for (int j = t; j < 1024; j += 128) {
            int r = j >> 4, q = j & 15;
            float4 v4 = *(const float4*)(src + r * 256 + wc * 64 + q * 4);
            vs[r][q * 4 + 0] = v4.x; vs[r][q * 4 + 1] = v4.y;
            vs[r][q * 4 + 2] = v4.z; vs[r][q * 4 + 3] = v4.w;
        }
        for (int j = t; j < 512; j += 128) {
            int k = j >> 3, q = j & 7;
            *(float4*)&es[k][q * 4] = *(const float4*)(g_etab + (wc * 64 + k) * 32 + q * 4);
        }
        __syncthreads();
        #pragma unroll 8
        for (int kk = 0; kk < 64; kk++) {
            float a0 = vs[r0 + 0][kk], a1 = vs[r0 + 1][kk];
            float a2 = vs[r0 + 2][kk], a3 = vs[r0 + 3][kk];
            float4 bf = *(const float4*)&es[kk][c0];
            acc[0][0] += a0 * bf.x; acc[0][1] += a0 * bf.y; acc[0][2] += a0 * bf.z; acc[0][3] += a0 * bf.w;
            acc[1][0] += a1 * bf.x; acc[1][1] += a1 * bf.y; acc[1][2] += a1 * bf.z; acc[1][3] += a1 * bf.w;
            acc[2][0] += a2 * bf.x; acc[2][1] += a2 * bf.y; acc[2][2] += a2 * bf.z; acc[2][3] += a2 * bf.w;
            acc[3][0] += a3 * bf.x; acc[3][1] += a3 * bf.y; acc[3][2] += a3 * bf.z; acc[3][3] += a3 * bf.w;
        }
    }
    #pragma unroll
    for (int i = 0; i < 4; i++)
        *(float4*)(g_a + (size_t)(rowbase + r0 + i) * 32 + c0) =
            make_float4(acc[i][0], acc[i][1], acc[i][2], acc[i][3]);
}

// ---------------- y-DFT GEMM, K-split x4: per (2bc, ks): partial C --------
__global__ void __launch_bounds__(128) k_ydft() {
    __shared__ float ts[64][65];      // [k within chunk][out row]
    __shared__ float as[64][36];      // [k within chunk][col = bcq*16+kx]
    int t = threadIdx.x;
    int ks = blockIdx.x & 3;
    int bc0 = (blockIdx.x >> 2) * 2;
    int rg = t >> 3, cg = t & 7;
    int r0 = rg * 4, c0 = cg * 4;
    float acc[4][4] = {};
    for (int ci = 0; ci < 2; ci++) {
        int ch = ks * 2 + ci;
        int h0 = ch * 32, k0 = ch * 64;
        __syncthreads();
        for (int j = t; j < 1024; j += 128) {
            int row = j >> 4, q = j & 15;
            float4 v4 = *(const float4*)(g_T + row * 512 + k0 + q * 4);
            ts[q * 4 + 0][row] = v4.x; ts[q * 4 + 1][row] = v4.y;
            ts[q * 4 + 2][row] = v4.z; ts[q * 4 + 3][row] = v4.w;
        }
        for (int j = t; j < 512; j += 128) {
            int bcq = j >> 8, rem = j & 255, hh = rem >> 3, q = rem & 7;
            float4 v4 = *(const float4*)(g_a + (size_t)((bc0 + bcq) * 256 + h0 + hh) * 32 + q * 4);
            int n0 = bcq * 16 + q * 2;
            as[2 * hh + 0][n0] = v4.x;     as[2 * hh + 1][n0] = v4.y;
            as[2 * hh + 0][n0 + 1] = v4.z; as[2 * hh + 1][n0 + 1] = v4.w;
        }
        __syncthreads();
        #pragma unroll 8
        for (int kk = 0; kk < 64; kk++) {
            float a0 = ts[kk][r0 + 0], a1 = ts[kk][r0 + 1];
            float a2 = ts[kk][r0 + 2], a3 = ts[kk][r0 + 3];
            float4 bf = *(const float4*)&as[kk][c0];
            acc[0][0] += a0 * bf.x; acc[0][1] += a0 * bf.y; acc[0][2] += a0 * bf.z; acc[0][3] += a0 * bf.w;
            acc[1][0] += a1 * bf.x; acc[1][1] += a1 * bf.y; acc[1][2] += a1 * bf.z; acc[1][3] += a1 * bf.w;
            acc[2][0] += a2 * bf.x; acc[2][1] += a2 * bf.y; acc[2][2] += a2 * bf.z; acc[2][3] += a2 * bf.w;
            acc[3][0] += a3 * bf.x; acc[3][1] += a3 * bf.y; acc[3][2] += a3 * bf.z; acc[3][3] += a3 * bf.w;
        }
    }
    float* vout = g_vftp + (size_t)ks * (Bn * Cn * 1024);
    #pragma unroll
    for (int i = 0; i < 4; i++) {
        int r = r0 + i, m = r >> 1, ri = r & 1;
        #pragma unroll
        for (int j = 0; j < 4; j++) {
            int c = c0 + j, bcq = c >> 4, kx = c & 15;
            vout[(bc0 + bcq) * 1024 + m * 32 + kx * 2 + ri] = acc[i][j];
        }
    }
}

// ---------------- per-mode 16x16 complex channel mixing (sums partials) --
__global__ void k_mix(const float* __restrict__ w1r, const float* __restrict__ w1i,
                      const float* __restrict__ w2r, const float* __restrict__ w2i,
                      int l) {
    int tid = blockIdx.x * blockDim.x + threadIdx.x;   // 131072
    int kx = tid & 15;
    int m = (tid >> 4) & 31;
    int o = (tid >> 9) & 15;
    int b = tid >> 13;
    int mm = m & 15;
    const float* wr = (m < 16) ? w1r : w2r;
    const float* wi = (m < 16) ? w1i : w2i;
    const int P = Bn * Cn * 1024;
    float accr = 0.f, acci = 0.f;
    #pragma unroll
    for (int i = 0; i < 16; i++) {
        int vidx = (b * 16 + i) * 1024 + m * 32 + kx * 2;
        float2 p0 = *(const float2*)(g_vftp + vidx);
        float2 p1 = *(const float2*)(g_vftp + P + vidx);
        float2 p2 = *(const float2*)(g_vftp + 2 * P + vidx);
        float2 p3 = *(const float2*)(g_vftp + 3 * P + vidx);
        float vr = (p0.x + p1.x) + (p2.x + p3.x);
        float vv = (p0.y + p1.y) + (p2.y + p3.y);
        int widx = (((l * 16 + i) * 16 + o) * 256) + mm * 16 + kx;
        float wrv = wr[widx], wiv = wi[widx];
        accr += vr * wrv - vv * wiv;
        acci += vr * wiv + vv * wrv;
    }
    int outi = (b * 16 + o) * 1024 + m * 32 + kx * 2;
    g_mix[outi + 0] = accr;
    g_mix[outi + 1] = acci;
}

// ---------------- h-synthesis GEMM per bc: C[512,16] = E3[512,64] x M ----
__global__ void __launch_bounds__(256) k_hsynth() {
    __shared__ float mixT[16][68];    // [kx][2m+p]
    int t = threadIdx.x;
    int bc = blockIdx.x;
    {
        float4 v4 = *(const float4*)(g_mix + (size_t)bc * 1024 + t * 4);
        int i4 = t * 4;
        #pragma unroll
        for (int e = 0; e < 4; e++) {
            int idx = i4 + e;
            int m = idx >> 5, rem = idx & 31, kx = rem >> 1, p = rem & 1;
            float val = (e == 0) ? v4.x : (e == 1) ? v4.y : (e == 2) ? v4.z : v4.w;
            mixT[kx][2 * m + p] = val;
        }
    }
    __syncthreads();
    int rg = t >> 3, cg = t & 7;
    float acc[16][2] = {};
    for (int ks = 0; ks < 64; ks += 4) {
        float4 bf0 = *(const float4*)&mixT[cg * 2 + 0][ks];
        float4 bf1 = *(const float4*)&mixT[cg * 2 + 1][ks];
        #pragma unroll
        for (int i = 0; i < 16; i++) {
            float4 af = *(const float4*)(g_E3 + (size_t)(32 * i + rg) * 64 + ks);
            acc[i][0] += af.x * bf0.x + af.y * bf0.y + af.z * bf0.z + af.w * bf0.w;
            acc[i][1] += af.x * bf1.x + af.y * bf1.y + af.z * bf1.z + af.w * bf1.w;
        }
    }
    #pragma unroll
    for (int i = 0; i < 16; i++) {
        int r = 32 * i + rg, h = r >> 1, ro = r & 1;
        #pragma unroll
        for (int jj = 0; jj < 2; jj++) {
            int kx = cg * 2 + jj;
            float sc = (kx == 0) ? (1.0f / 65536.0f) : (2.0f / 65536.0f);
            g_gs[(size_t)(bc * 256 + h) * 32 + kx * 2 + ro] = acc[i][jj] * sc;
        }
    }
}

// ---------------- fused w-synth + skip + gelu via tf32 mma.sync ----------
// Block per (b,h), 256 thr = 8 warps. OUT[16,256] = A[16,48] x B[48,256],
// A = [skw | gr | -gi], B = [V ; cos ; sin]. Warp owns 32 consecutive w.
__global__ void __launch_bounds__(256) k_wsynth(const float* __restrict__ skw,
                         const float* __restrict__ skb,
                         int l, int act, int flip) {
    __shared__ float vs[16][260];     // stride 260: conflict-free quad reads
    __shared__ float ms[16][52];      // [o][0:16 skw | 16:32 gr | 32:48 -gi]
    __shared__ float sb[16];
    const float* __restrict__ vin = flip ? g_v1 : g_v0;
    float* __restrict__ vout = flip ? g_v0 : g_v1;
    int t = threadIdx.x;
    int lane = t & 31, warp = t >> 5;
    int b = blockIdx.x >> 8, h = blockIdx.x & 255;
    for (int j = t; j < 1024; j += 256) {
        int c = j >> 6, q = j & 63;
        float4 v4 = *(const float4*)(vin + ((size_t)(b * 16 + c) * 256 + h) * 256 + q * 4);
        vs[c][q * 4 + 0] = v4.x; vs[c][q * 4 + 1] = v4.y;
        vs[c][q * 4 + 2] = v4.z; vs[c][q * 4 + 3] = v4.w;
    }
    {
        int c = t >> 4, k = t & 15;
        ms[c][k] = skw[l * 256 + c * 16 + k];
        int base = ((size_t)(b * 16 + c) * 256 + h) * 32 + k * 2;
        ms[c][16 + k] = g_gs[base];
        ms[c][32 + k] = -g_gs[base + 1];
        if (t < 16) sb[t] = skb[l * 16 + t];
    }
    __syncthreads();
    int gid = lane >> 2, tig = lane & 3;
    // A fragments: 6 k-slices x 4 regs (rows gid, gid+8; cols ks*8+tig, +4)
    unsigned a[6][4];
    #pragma unroll
    for (int ks = 0; ks < 6; ks++) {
        int c0 = ks * 8 + tig;
        a[ks][0] = f2tf32(ms[gid][c0]);
        a[ks][1] = f2tf32(ms[gid + 8][c0]);
        a[ks][2] = f2tf32(ms[gid][c0 + 4]);
        a[ks][3] = f2tf32(ms[gid + 8][c0 + 4]);
    }
    float bias0 = sb[gid], bias1 = sb[gid + 8];
    float* out0 = vout + ((size_t)(b * 16 + gid) * 256 + h) * 256;
    float* out1 = vout + ((size_t)(b * 16 + gid + 8) * 256 + h) * 256;
    #pragma unroll
    for (int nt = 0; nt < 4; nt++) {
        int n = warp * 32 + nt * 8 + gid;
        unsigned bf[6][2];
        bf[0][0] = f2tf32(vs[tig][n]);        bf[0][1] = f2tf32(vs[tig + 4][n]);
        bf[1][0] = f2tf32(vs[8 + tig][n]);    bf[1][1] = f2tf32(vs[12 + tig][n]);
        bf[2][0] = f2tf32(g_xc[tig * 256 + n]);
        bf[2][1] = f2tf32(g_xc[(tig + 4) * 256 + n]);
        bf[3][0] = f2tf32(g_xc[(8 + tig) * 256 + n]);
        bf[3][1] = f2tf32(g_xc[(12 + tig) * 256 + n]);
        bf[4][0] = f2tf32(g_xs[tig * 256 + n]);
        bf[4][1] = f2tf32(g_xs[(tig + 4) * 256 + n]);
        bf[5][0] = f2tf32(g_xs[(8 + tig) * 256 + n]);
        bf[5][1] = f2tf32(g_xs[(12 + tig) * 256 + n]);
        float d0 = 0.f, d1 = 0.f, d2 = 0.f, d3 = 0.f;
        #pragma unroll
        for (int ks = 0; ks < 6; ks++) {
            asm volatile(
                "mma.sync.aligned.m16n8k8.row.col.f32.tf32.tf32.f32 "
                "{%0,%1,%2,%3}, {%4,%5,%6,%7}, {%8,%9}, {%0,%1,%2,%3};\n"
                : "+f"(d0), "+f"(d1), "+f"(d2), "+f"(d3)
                : "r"(a[ks][0]), "r"(a[ks][1]), "r"(a[ks][2]), "r"(a[ks][3]),
                  "r"(bf[ks][0]), "r"(bf[ks][1]));
        }
        d0 += bias0; d1 += bias0; d2 += bias1; d3 += bias1;
        if (act) {
            d0 = gelu_t(d0); d1 = gelu_t(d1);
            d2 = gelu_t(d2); d3 = gelu_t(d3);
        }
        int w = warp * 32 + nt * 8 + 2 * tig;
        *(float2*)(out0 + w) = make_float2(d0, d1);
        *(float2*)(out1 + w) = make_float2(d2, d3);
    }
}

// ---------------- proj1 (16->128) + gelu + pooling via tf32 mma.sync -----
__global__ void __launch_bounds__(128) k_proj(const float* __restrict__ w1,
                                              const float* __restrict__ b1) {
    __shared__ float vs[16][72];          // stride 72: conflict-free B reads
    int t = threadIdx.x;
    int lane = t & 31, warp = t >> 5;
    int blk = blockIdx.x;                 // b*1024 + h*4 + wc
    int wc = blk & 3, h = (blk >> 2) & 255, b = blk >> 10;
    const float* vrow = g_v0 + ((size_t)(b * 16) * 256 + h) * 256 + wc * 64;
    for (int j = t; j < 256; j += 128) {  // 256 float4 = 16ch x 64px
        int c = j >> 4, p4 = j & 15;
        float4 v4 = ((const float4*)(vrow + (size_t)c * 65536))[p4];
        vs[c][p4 * 4 + 0] = v4.x; vs[c][p4 * 4 + 1] = v4.y;
        vs[c][p4 * 4 + 2] = v4.z; vs[c][p4 * 4 + 3] = v4.w;
    }
    int gid = lane >> 2, tig = lane & 3;  // groupID, threadID_in_group
    int m_base = warp * 32;
    unsigned a[2][2][4];
    float bb[2][2];
    #pragma unroll
    for (int mt = 0; mt < 2; mt++) {
        int r_lo = m_base + mt * 16 + gid;
        bb[mt][0] = b1[r_lo];
        bb[mt][1] = b1[r_lo + 8];
        #pragma unroll
        for (int ks = 0; ks < 2; ks++) {
            int c_lo = ks * 8 + tig;
            a[mt][ks][0] = f2tf32(w1[r_lo * 16 + c_lo]);
            a[mt][ks][1] = f2tf32(w1[(r_lo + 8) * 16 + c_lo]);
            a[mt][ks][2] = f2tf32(w1[r_lo * 16 + c_lo + 4]);
            a[mt][ks][3] = f2tf32(w1[(r_lo + 8) * 16 + c_lo + 4]);
        }
    }
    __syncthreads();
    float s[2][2] = {};                    // pooled sums per (mt, row-half)
    #pragma unroll
    for (int nt = 0; nt < 8; nt++) {
        int n = nt * 8 + gid;
        unsigned bfr[2][2];
        #pragma unroll
        for (int ks = 0; ks < 2; ks++) {
            bfr[ks][0] = f2tf32(vs[ks * 8 + tig][n]);
            bfr[ks][1] = f2tf32(vs[ks * 8 + tig + 4][n]);
        }
        #pragma unroll
        for (int mt = 0; mt < 2; mt++) {
            float d0 = 0.f, d1 = 0.f, d2 = 0.f, d3 = 0.f;
            #pragma unroll
            for (int ks = 0; ks < 2; ks++) {
                asm volatile(
                    "mma.sync.aligned.m16n8k8.row.col.f32.tf32.tf32.f32 "
                    "{%0,%1,%2,%3}, {%4,%5,%6,%7}, {%8,%9}, {%0,%1,%2,%3};\n"
                    : "+f"(d0), "+f"(d1), "+f"(d2), "+f"(d3)
                    : "r"(a[mt][ks][0]), "r"(a[mt][ks][1]),
                      "r"(a[mt][ks][2]), "r"(a[mt][ks][3]),
                      "r"(bfr[ks][0]), "r"(bfr[ks][1]));
            }
            s[mt][0] += gelu_t(d0 + bb[mt][0]) + gelu_t(d1 + bb[mt][0]);
            s[mt][1] += gelu_t(d2 + bb[mt][1]) + gelu_t(d3 + bb[mt][1]);
        }
    }
    #pragma unroll
    for (int mt = 0; mt < 2; mt++) {
        #pragma unroll
        for (int hh = 0; hh < 2; hh++) {
            float v = s[mt][hh];
            v += __shfl_xor_sync(0xFFFFFFFFu, v, 1);
            v += __shfl_xor_sync(0xFFFFFFFFu, v, 2);
            s[mt][hh] = v;
        }
    }
    if (tig == 0) {
        float* dst = g_pool + (size_t)blk * 128;
        #pragma unroll
        for (int mt = 0; mt < 2; mt++) {
            dst[m_base + mt * 16 + gid]     = s[mt][0];
            dst[m_base + mt * 16 + gid + 8] = s[mt][1];
        }
    }
}

// ---------------- final reduce + proj2 on pooled vector + head -----------
__global__ void k_head(const float* __restrict__ w2, const float* __restrict__ b2,
                       const float* __restrict__ hw_, const float* __restrict__ hb,
                       float* __restrict__ out) {
    __shared__ float pq[128];
    __shared__ float f[64];
    int b = blockIdx.x, t = threadIdx.x;
    float s = 0.f;
    for (int k = 0; k < 1024; k++)
        s += g_pool[((size_t)(b * 1024 + k)) * 128 + t];
    pq[t] = s * (1.0f / 65536.0f);
    __syncthreads();
    if (t < 64) {
        float a = b2[t];
        #pragma unroll 8
        for (int i = 0; i < 128; i++) a += w2[t * 128 + i] * pq[i];
        f[t] = a;
    }
    __syncthreads();
    if (t < 2) {
        float a = hb[t];
        #pragma unroll
        for (int o = 0; o < 64; o++) a += hw_[t * 64 + o] * f[o];
        float e = __expf(2.0f * a);
        out[b * 2 + t] = 1.0f - 2.0f / (e + 1.0f);
    }
}

extern "C" void kernel_launch(void* const* d_in, const int* in_sizes, int n_in,
                              void* d_out, int out_size) {
    const float* x    = (const float*)d_in[0];
    const float* lw   = (const float*)d_in[1];
    const float* lb   = (const float*)d_in[2];
    const float* w1r  = (const float*)d_in[3];
    const float* w1i  = (const float*)d_in[4];
    const float* w2r  = (const float*)d_in[5];
    const float* w2i  = (const float*)d_in[6];
    const float* skw  = (const float*)d_in[7];
    const float* skb  = (const float*)d_in[8];
    const float* pw1  = (const float*)d_in[9];
    const float* pb1  = (const float*)d_in[10];
    const float* pw2  = (const float*)d_in[11];
    const float* pb2  = (const float*)d_in[12];
    const float* hw_  = (const float*)d_in[13];
    const float* hb   = (const float*)d_in[14];
    float* out = (float*)d_out;

    k_tw<<<320, 256>>>();
    k_lift<<<BCHW / 256, 256>>>(x, lw, lb);
    for (int l = 0; l < Ln; l++) {
        int flip = l & 1;                    // input buffer: 0 -> g_v0
        k_xdft  <<<1024, 128>>>(flip);
        k_ydft  <<<512, 128>>>();
        k_mix   <<<512, 256>>>(w1r, w1i, w2r, w2i, l);
        k_hsynth<<<256, 256>>>();
        k_wsynth<<<4096, 256>>>(skw, skb, l, (l < Ln - 1) ? 1 : 0, flip);
    }
    // after 4 layers result is in g_v0
    k_proj<<<16384, 128>>>(pw1, pb1);
    k_head<<<Bn, 128>>>(pw2, pb2, hw_, hb, out);
}

// round 11
// speedup vs baseline: 1.9418x; 1.0283x over previous
#include <cuda_runtime.h>

// FNO with global head. B=16, C=16, H=W=256, L=4, modes 16x16.
// R11: R10 base (610us) + k_xdft converted to 3xTF32 error-compensated mma.

#define Bn 16
#define Cn 16
#define Hn 256
#define Wn 256
#define Ln 4
#define BCHW (Bn*Cn*Hn*Wn)

__device__ float g_v0[BCHW];                 // ping
__device__ float g_v1[BCHW];                 // pong
__device__ float g_a  [Bn*Cn*Hn*32];         // x-DFT result [row][2kx+ri]
__device__ float g_vftp[4*Bn*Cn*1024];       // ydft partials [ks][bc][m*32+kx*2+ri]
__device__ float g_mix[Bn*Cn*32*32];         // after channel mix
__device__ float g_gs [Bn*Cn*Hn*32];         // h-synth [bc*256+h][kx*2+ri]
__device__ float g_ehi[256*32];              // xdft E hi (tf32-rounded)
__device__ float g_elo[256*32];              // xdft E lo (residual, tf32-repr)
__device__ float g_xc[16*256];               // wsynth cos[kx][w]
__device__ float g_xs[16*256];               // wsynth sin[kx][w]
__device__ float g_T [64*512];               // ydft T: [2m+ri][2h+p]
__device__ float g_E3[512*64];               // hsynth E3: [2h+ro][2m+p]
__device__ float g_pool[Bn*1024*128];        // proj partial sums

__device__ __forceinline__ float gelu_t(float x) {
    const float k0 = 0.7978845608028654f;
    const float k1 = 0.044715f;
    float y = k0 * x * (1.0f + k1 * x * x);
    float th;
    asm("tanh.approx.f32 %0, %1;" : "=f"(th) : "f"(y));
    return 0.5f * x * (1.0f + th);
}

__device__ __forceinline__ unsigned f2tf32(float f) {
    unsigned u;
    asm("cvt.rna.tf32.f32 %0, %1;" : "=r"(u) : "f"(f));
    return u;
}

#define MMA_TF32(D, A, B0, B1)                                            \
    asm volatile(                                                          \
        "mma.sync.aligned.m16n8k8.row.col.f32.tf32.tf32.f32 "             \
        "{%0,%1,%2,%3}, {%4,%5,%6,%7}, {%8,%9}, {%0,%1,%2,%3};\n"         \
        : "+f"(D[0]), "+f"(D[1]), "+f"(D[2]), "+f"(D[3])                   \
        : "r"(A[0]), "r"(A[1]), "r"(A[2]), "r"(A[3]), "r"(B0), "r"(B1))

// ---------------- build all constant tables ----------------
__global__ void k_tw() {
    int j = blockIdx.x * 256 + threadIdx.x;
    if (j < 8192) {                                   // g_ehi / g_elo
        int w = j >> 5, c = j & 31;
        int kx = c >> 1, ri = c & 1;
        float ang = (float)((kx * w) & 255) / 128.0f;
        float e = ri ? -sinpif(ang) : cospif(ang);
        float hi = __uint_as_float(f2tf32(e) & 0xFFFFE000u);
        // f2tf32 keeps full 32 bits? cvt.rna.tf32 zeroes low 13 bits already;
        // mask is belt-and-braces.
        g_ehi[j] = hi;
        g_elo[j] = __uint_as_float(f2tf32(e - hi));
    } else if (j < 12288) {                           // g_xc
        int e = j - 8192;
        int kx = e >> 8, w = e & 255;
        g_xc[e] = cospif((float)((kx * w) & 255) / 128.0f);
    } else if (j < 16384) {                           // g_xs
        int e = j - 12288;
        int kx = e >> 8, w = e & 255;
        g_xs[e] = sinpif((float)((kx * w) & 255) / 128.0f);
    } else if (j < 49152) {                           // g_T [2m+ri][2h+p]
        int e = j - 16384;
        int row = e >> 9, col = e & 511;
        int m = row >> 1, ri = row & 1;
        int h = col >> 1, p = col & 1;
        int ky = (m < 16) ? m : (m + 224);
        float ang = (float)((ky * h) & 255) / 128.0f;
        float cy = cospif(ang), sy = sinpif(ang);
        g_T[e] = (ri == 0) ? (p == 0 ? cy : sy) : (p == 0 ? -sy : cy);
    } else if (j < 81920) {                           // g_E3 [2h+ro][2m+p]
        int e = j - 49152;
        int row = e >> 6, col = e & 63;
        int h = row >> 1, ro = row & 1;
        int m = col >> 1, p = col & 1;
        int ky = (m < 16) ? m : (m + 224);
        float ang = (float)((ky * h) & 255) / 128.0f;
        float cy = cospif(ang), sy = sinpif(ang);
        g_E3[e] = (ro == 0) ? (p == 0 ? cy : -sy) : (p == 0 ? sy : cy);
    }
}

// ---------------- lifting 1 -> 16 channels ----------------
__global__ void k_lift(const float* __restrict__ x,
                       const float* __restrict__ lw,
                       const float* __restrict__ lb) {
    int idx = blockIdx.x * blockDim.x + threadIdx.x;
    int w = idx & 255;
    int h = (idx >> 8) & 255;
    int c = (idx >> 16) & 15;
    int b = idx >> 20;
    float xv = x[(b << 16) | (h << 8) | w];
    g_v0[idx] = lw[c] * xv + lb[c];
}

// ---------------- x-DFT via 3xTF32 mma: C[64,32] = V[64,256] x E[256,32] --
// 128 thr = 4 warps (m-tiles). 4 n-tiles, 32 k-slices, 3 compensation terms.
__global__ void __launch_bounds__(128) k_xdft(int flip) {
    __shared__ float vs[64][68];      // V chunk; banks 4*gid+tig unique
    __shared__ float eh[64][40];      // Ehi chunk; banks 8*tig+gid unique
    __shared__ float el[64][40];      // Elo chunk
    const float* __restrict__ vin = flip ? g_v1 : g_v0;
    int t = threadIdx.x;
    int lane = t & 31, warp = t >> 5;
    int gid = lane >> 2, tig = lane & 3;
    int rowbase = blockIdx.x * 64;
    const float* src = vin + (size_t)rowbase * 256;
    float d[4][4] = {};
    for (int kc = 0; kc < 4; kc++) {
        __syncthreads();
        for (int j = t; j < 1024; j += 128) {
            int r = j >> 4, q = j & 15;
            float4 v4 = *(const float4*)(src + r * 256 + kc * 64 + q * 4);
            vs[r][q * 4 + 0] = v4.x; vs[r][q * 4 + 1] = v4.y;
            vs[r][q * 4 + 2] = v4.z; vs[r][q * 4 + 3] = v4.w;
        }
        for (int j = t; j < 512; j += 128) {
            int k = j >> 3, q = j & 7;
            float4 h4 = *(const float4*)(g_ehi + (size_t)(kc * 64 + k) * 32 + q * 4);
            eh[k][q * 4 + 0] = h4.x; eh[k][q * 4 + 1] = h4.y;
            eh[k][q * 4 + 2] = h4.z; eh[k][q * 4 + 3] = h4.w;
            float4 l4 = *(const float4*)(g_elo + (size_t)(kc * 64 + k) * 32 + q * 4);
            el[k][q * 4 + 0] = l4.x; el[k][q * 4 + 1] = l4.y;
            el[k][q * 4 + 2] = l4.z; el[k][q * 4 + 3] = l4.w;
        }
        __syncthreads();
        #pragma unroll
        for (int ks = 0; ks < 8; ks++) {
            int kk = ks * 8;
            int m0 = warp * 16 + gid;
            float va[4];
            va[0] = vs[m0][kk + tig];     va[1] = vs[m0 + 8][kk + tig];
            va[2] = vs[m0][kk + tig + 4]; va[3] = vs[m0 + 8][kk + tig + 4];
            unsigned ah[4], al_[4];
            #pragma unroll
            for (int i = 0; i < 4; i++) {
                ah[i] = f2tf32(va[i]);
                al_[i] = f2tf32(va[i] - __uint_as_float(ah[i]));
            }
            #pragma unroll
            for (int nt = 0; nt < 4; nt++) {
                int n = nt * 8 + gid;
                unsigned bh0 = __float_as_uint(eh[kk + tig][n]);
                unsigned bh1 = __float_as_uint(eh[kk + tig + 4][n]);
                unsigned bl0 = __float_as_uint(el[kk + tig][n]);
                unsigned bl1 = __float_as_uint(el[kk + tig + 4][n]);
                MMA_TF32(d[nt], ah, bh0, bh1);
                MMA_TF32(d[nt], al_, bh0, bh1);
                MMA_TF32(d[nt], ah, bl0, bl1);
            }
        }
    }
    int m0 = rowbase + warp * 16 + gid;
    #pragma unroll
    for (int nt = 0; nt < 4; nt++) {
        int c0 = nt * 8 + 2 * tig;
        *(float2*)(g_a + (size_t)m0 * 32 + c0) = make_float2(d[nt][0], d[nt][1]);
        *(float2*)(g_a + (size_t)(m0 + 8) * 32 + c0) = make_float2(d[nt][2], d[nt][3]);
    }
}

// ---------------- y-DFT GEMM, K-split x4: per (2bc, ks): partial C --------
__global__ void __launch_bounds__(128) k_ydft() {
    __shared__ float ts[64][65];      // [k within chunk][out row]
    __shared__ float as[64][36];      // [k within chunk][col = bcq*16+kx]
    int t = threadIdx.x;
    int ks = blockIdx.x & 3;
    int bc0 = (blockIdx.x >> 2) * 2;
    int rg = t >> 3, cg = t & 7;
    int r0 = rg * 4, c0 = cg * 4;
    float acc[4][4] = {};
    for (int ci = 0; ci < 2; ci++) {
        int ch = ks * 2 + ci;
        int h0 = ch * 32, k0 = ch * 64;
        __syncthreads();
        for (int j = t; j < 1024; j += 128) {
            int row = j >> 4, q = j & 15;
            float4 v4 = *(const float4*)(g_T + row * 512 + k0 + q * 4);
            ts[q * 4 + 0][row] = v4.x; ts[q * 4 + 1][row] = v4.y;
            ts[q * 4 + 2][row] = v4.z; ts[q * 4 + 3][row] = v4.w;
        }
        for (int j = t; j < 512; j += 128) {
            int bcq = j >> 8, rem = j & 255, hh = rem >> 3, q = rem & 7;
            float4 v4 = *(const float4*)(g_a + (size_t)((bc0 + bcq) * 256 + h0 + hh) * 32 + q * 4);
            int n0 = bcq * 16 + q * 2;
            as[2 * hh + 0][n0] = v4.x;     as[2 * hh + 1][n0] = v4.y;
            as[2 * hh + 0][n0 + 1] = v4.z; as[2 * hh + 1][n0 + 1] = v4.w;
        }
        __syncthreads();
        #pragma unroll 8
        for (int kk = 0; kk < 64; kk++) {
            float a0 = ts[kk][r0 + 0], a1 = ts[kk][r0 + 1];
            float a2 = ts[kk][r0 + 2], a3 = ts[kk][r0 + 3];
            float4 bf = *(const float4*)&as[kk][c0];
            acc[0][0] += a0 * bf.x; acc[0][1] += a0 * bf.y; acc[0][2] += a0 * bf.z; acc[0][3] += a0 * bf.w;
            acc[1][0] += a1 * bf.x; acc[1][1] += a1 * bf.y; acc[1][2] += a1 * bf.z; acc[1][3] += a1 * bf.w;
            acc[2][0] += a2 * bf.x; acc[2][1] += a2 * bf.y; acc[2][2] += a2 * bf.z; acc[2][3] += a2 * bf.w;
            acc[3][0] += a3 * bf.x; acc[3][1] += a3 * bf.y; acc[3][2] += a3 * bf.z; acc[3][3] += a3 * bf.w;
        }
    }
    float* vout = g_vftp + (size_t)ks * (Bn * Cn * 1024);
    #pragma unroll
    for (int i = 0; i < 4; i++) {
        int r = r0 + i, m = r >> 1, ri = r & 1;
        #pragma unroll
        for (int j = 0; j < 4; j++) {
            int c = c0 + j, bcq = c >> 4, kx = c & 15;
            vout[(bc0 + bcq) * 1024 + m * 32 + kx * 2 + ri] = acc[i][j];
        }
    }
}

// ---------------- per-mode 16x16 complex channel mixing (sums partials) --
__global__ void k_mix(const float* __restrict__ w1r, const float* __restrict__ w1i,
                      const float* __restrict__ w2r, const float* __restrict__ w2i,
                      int l) {
    int tid = blockIdx.x * blockDim.x + threadIdx.x;   // 131072
    int kx = tid & 15;
    int m = (tid >> 4) & 31;
    int o = (tid >> 9) & 15;
    int b = tid >> 13;
    int mm = m & 15;
    const float* wr = (m < 16) ? w1r : w2r;
    const float* wi = (m < 16) ? w1i : w2i;
    const int P = Bn * Cn * 1024;
    float accr = 0.f, acci = 0.f;
    #pragma unroll
    for (int i = 0; i < 16; i++) {
        int vidx = (b * 16 + i) * 1024 + m * 32 + kx * 2;
        float2 p0 = *(const float2*)(g_vftp + vidx);
        float2 p1 = *(const float2*)(g_vftp + P + vidx);
        float2 p2 = *(const float2*)(g_vftp + 2 * P + vidx);
        float2 p3 = *(const float2*)(g_vftp + 3 * P + vidx);
        float vr = (p0.x + p1.x) + (p2.x + p3.x);
        float vv = (p0.y + p1.y) + (p2.y + p3.y);
        int widx = (((l * 16 + i) * 16 + o) * 256) + mm * 16 + kx;
        float wrv = wr[widx], wiv = wi[widx];
        accr += vr * wrv - vv * wiv;
        acci += vr * wiv + vv * wrv;
    }
    int outi = (b * 16 + o) * 1024 + m * 32 + kx * 2;
    g_mix[outi + 0] = accr;
    g_mix[outi + 1] = acci;
}

// ---------------- h-synthesis GEMM per bc: C[512,16] = E3[512,64] x M ----
__global__ void __launch_bounds__(256) k_hsynth() {
    __shared__ float mixT[16][68];    // [kx][2m+p]
    int t = threadIdx.x;
    int bc = blockIdx.x;
    {
        float4 v4 = *(const float4*)(g_mix + (size_t)bc * 1024 + t * 4);
        int i4 = t * 4;
        #pragma unroll
        for (int e = 0; e < 4; e++) {
            int idx = i4 + e;
            int m = idx >> 5, rem = idx & 31, kx = rem >> 1, p = rem & 1;
            float val = (e == 0) ? v4.x : (e == 1) ? v4.y : (e == 2) ? v4.z : v4.w;
            mixT[kx][2 * m + p] = val;
        }
    }
    __syncthreads();
    int rg = t >> 3, cg = t & 7;
    float acc[16][2] = {};
    for (int ks = 0; ks < 64; ks += 4) {
        float4 bf0 = *(const float4*)&mixT[cg * 2 + 0][ks];
        float4 bf1 = *(const float4*)&mixT[cg * 2 + 1][ks];
        #pragma unroll
        for (int i = 0; i < 16; i++) {
            float4 af = *(const float4*)(g_E3 + (size_t)(32 * i + rg) * 64 + ks);
            acc[i][0] += af.x * bf0.x + af.y * bf0.y + af.z * bf0.z + af.w * bf0.w;
            acc[i][1] += af.x * bf1.x + af.y * bf1.y + af.z * bf1.z + af.w * bf1.w;
        }
    }
    #pragma unroll
    for (int i = 0; i < 16; i++) {
        int r = 32 * i + rg, h = r >> 1, ro = r & 1;
        #pragma unroll
        for (int jj = 0; jj < 2; jj++) {
            int kx = cg * 2 + jj;
            float sc = (kx == 0) ? (1.0f / 65536.0f) : (2.0f / 65536.0f);
            g_gs[(size_t)(bc * 256 + h) * 32 + kx * 2 + ro] = acc[i][jj] * sc;
        }
    }
}

// ---------------- fused w-synth + skip + gelu via tf32 mma.sync ----------
__global__ void __launch_bounds__(256) k_wsynth(const float* __restrict__ skw,
                         const float* __restrict__ skb,
                         int l, int act, int flip) {
    __shared__ float vs[16][260];     // stride 260: conflict-free quad reads
    __shared__ float ms[16][52];      // [o][0:16 skw | 16:32 gr | 32:48 -gi]
    __shared__ float sb[16];
    const float* __restrict__ vin = flip ? g_v1 : g_v0;
    float* __restrict__ vout = flip ? g_v0 : g_v1;
    int t = threadIdx.x;
    int lane = t & 31, warp = t >> 5;
    int b = blockIdx.x >> 8, h = blockIdx.x & 255;
    for (int j = t; j < 1024; j += 256) {
        int c = j >> 6, q = j & 63;
        float4 v4 = *(const float4*)(vin + ((size_t)(b * 16 + c) * 256 + h) * 256 + q * 4);
        vs[c][q * 4 + 0] = v4.x; vs[c][q * 4 + 1] = v4.y;
        vs[c][q * 4 + 2] = v4.z; vs[c][q * 4 + 3] = v4.w;
    }
    {
        int c = t >> 4, k = t & 15;
        ms[c][k] = skw[l * 256 + c * 16 + k];
        int base = ((size_t)(b * 16 + c) * 256 + h) * 32 + k * 2;
        ms[c][16 + k] = g_gs[base];
        ms[c][32 + k] = -g_gs[base + 1];
        if (t < 16) sb[t] = skb[l * 16 + t];
    }
    __syncthreads();
    int gid = lane >> 2, tig = lane & 3;
    unsigned a[6][4];
    #pragma unroll
    for (int ks = 0; ks < 6; ks++) {
        int c0 = ks * 8 + tig;
        a[ks][0] = f2tf32(ms[gid][c0]);
        a[ks][1] = f2tf32(ms[gid + 8][c0]);
        a[ks][2] = f2tf32(ms[gid][c0 + 4]);
        a[ks][3] = f2tf32(ms[gid + 8][c0 + 4]);
    }
    float bias0 = sb[gid], bias1 = sb[gid + 8];
    float* out0 = vout + ((size_t)(b * 16 + gid) * 256 + h) * 256;
    float* out1 = vout + ((size_t)(b * 16 + gid + 8) * 256 + h) * 256;
    #pragma unroll
    for (int nt = 0; nt < 4; nt++) {
        int n = warp * 32 + nt * 8 + gid;
        unsigned bf[6][2];
        bf[0][0] = f2tf32(vs[tig][n]);        bf[0][1] = f2tf32(vs[tig + 4][n]);
        bf[1][0] = f2tf32(vs[8 + tig][n]);    bf[1][1] = f2tf32(vs[12 + tig][n]);
        bf[2][0] = f2tf32(g_xc[tig * 256 + n]);
        bf[2][1] = f2tf32(g_xc[(tig + 4) * 256 + n]);
        bf[3][0] = f2tf32(g_xc[(8 + tig) * 256 + n]);
        bf[3][1] = f2tf32(g_xc[(12 + tig) * 256 + n]);
        bf[4][0] = f2tf32(g_xs[tig * 256 + n]);
        bf[4][1] = f2tf32(g_xs[(tig + 4) * 256 + n]);
        bf[5][0] = f2tf32(g_xs[(8 + tig) * 256 + n]);
        bf[5][1] = f2tf32(g_xs[(12 + tig) * 256 + n]);
        float d0 = 0.f, d1 = 0.f, d2 = 0.f, d3 = 0.f;
        #pragma unroll
        for (int ks = 0; ks < 6; ks++) {
            asm volatile(
                "mma.sync.aligned.m16n8k8.row.col.f32.tf32.tf32.f32 "
                "{%0,%1,%2,%3}, {%4,%5,%6,%7}, {%8,%9}, {%0,%1,%2,%3};\n"
                : "+f"(d0), "+f"(d1), "+f"(d2), "+f"(d3)
                : "r"(a[ks][0]), "r"(a[ks][1]), "r"(a[ks][2]), "r"(a[ks][3]),
                  "r"(bf[ks][0]), "r"(bf[ks][1]));
        }
        d0 += bias0; d1 += bias0; d2 += bias1; d3 += bias1;
        if (act) {
            d0 = gelu_t(d0); d1 = gelu_t(d1);
            d2 = gelu_t(d2); d3 = gelu_t(d3);
        }
        int w = warp * 32 + nt * 8 + 2 * tig;
        *(float2*)(out0 + w) = make_float2(d0, d1);
        *(float2*)(out1 + w) = make_float2(d2, d3);
    }
}

// ---------------- proj1 (16->128) + gelu + pooling via tf32 mma.sync -----
__global__ void __launch_bounds__(128) k_proj(const float* __restrict__ w1,
                                              const float* __restrict__ b1) {
    __shared__ float vs[16][72];          // stride 72: conflict-free B reads
    int t = threadIdx.x;
    int lane = t & 31, warp = t >> 5;
    int blk = blockIdx.x;                 // b*1024 + h*4 + wc
    int wc = blk & 3, h = (blk >> 2) & 255, b = blk >> 10;
    const float* vrow = g_v0 + ((size_t)(b * 16) * 256 + h) * 256 + wc * 64;
    for (int j = t; j < 256; j += 128) {  // 256 float4 = 16ch x 64px
        int c = j >> 4, p4 = j & 15;
        float4 v4 = ((const float4*)(vrow + (size_t)c * 65536))[p4];
        vs[c][p4 * 4 + 0] = v4.x; vs[c][p4 * 4 + 1] = v4.y;
        vs[c][p4 * 4 + 2] = v4.z; vs[c][p4 * 4 + 3] = v4.w;
    }
    int gid = lane >> 2, tig = lane & 3;  // groupID, threadID_in_group
    int m_base = warp * 32;
    unsigned a[2][2][4];
    float bb[2][2];
    #pragma unroll
    for (int mt = 0; mt < 2; mt++) {
        int r_lo = m_base + mt * 16 + gid;
        bb[mt][0] = b1[r_lo];
        bb[mt][1] = b1[r_lo + 8];
        #pragma unroll
        for (int ks = 0; ks < 2; ks++) {
            int c_lo = ks * 8 + tig;
            a[mt][ks][0] = f2tf32(w1[r_lo * 16 + c_lo]);
            a[mt][ks][1] = f2tf32(w1[(r_lo + 8) * 16 + c_lo]);
            a[mt][ks][2] = f2tf32(w1[r_lo * 16 + c_lo + 4]);
            a[mt][ks][3] = f2tf32(w1[(r_lo + 8) * 16 + c_lo + 4]);
        }
    }
    __syncthreads();
    float s[2][2] = {};                    // pooled sums per (mt, row-half)
    #pragma unroll
    for (int nt = 0; nt < 8; nt++) {
        int n = nt * 8 + gid;
        unsigned bfr[2][2];
        #pragma unroll
        for (int ks = 0; ks < 2; ks++) {
            bfr[ks][0] = f2tf32(vs[ks * 8 + tig][n]);
            bfr[ks][1] = f2tf32(vs[ks * 8 + tig + 4][n]);
        }
        #pragma unroll
        for (int mt = 0; mt < 2; mt++) {
            float d0 = 0.f, d1 = 0.f, d2 = 0.f, d3 = 0.f;
            #pragma unroll
            for (int ks = 0; ks < 2; ks++) {
                asm volatile(
                    "mma.sync.aligned.m16n8k8.row.col.f32.tf32.tf32.f32 "
                    "{%0,%1,%2,%3}, {%4,%5,%6,%7}, {%8,%9}, {%0,%1,%2,%3};\n"
                    : "+f"(d0), "+f"(d1), "+f"(d2), "+f"(d3)
                    : "r"(a[mt][ks][0]), "r"(a[mt][ks][1]),
                      "r"(a[mt][ks][2]), "r"(a[mt][ks][3]),
                      "r"(bfr[ks][0]), "r"(bfr[ks][1]));
            }
            s[mt][0] += gelu_t(d0 + bb[mt][0]) + gelu_t(d1 + bb[mt][0]);
            s[mt][1] += gelu_t(d2 + bb[mt][1]) + gelu_t(d3 + bb[mt][1]);
        }
    }
    #pragma unroll
    for (int mt = 0; mt < 2; mt++) {
        #pragma unroll
        for (int hh = 0; hh < 2; hh++) {
            float v = s[mt][hh];
            v += __shfl_xor_sync(0xFFFFFFFFu, v, 1);
            v += __shfl_xor_sync(0xFFFFFFFFu, v, 2);
            s[mt][hh] = v;
        }
    }
    if (tig == 0) {
        float* dst = g_pool + (size_t)blk * 128;
        #pragma unroll
        for (int mt = 0; mt < 2; mt++) {
            dst[m_base + mt * 16 + gid]     = s[mt][0];
            dst[m_base + mt * 16 + gid + 8] = s[mt][1];
        }
    }
}

// ---------------- final reduce + proj2 on pooled vector + head -----------
__global__ void k_head(const float* __restrict__ w2, const float* __restrict__ b2,
                       const float* __restrict__ hw_, const float* __restrict__ hb,
                       float* __restrict__ out) {
    __shared__ float pq[128];
    __shared__ float f[64];
    int b = blockIdx.x, t = threadIdx.x;
    float s = 0.f;
    for (int k = 0; k < 1024; k++)
        s += g_pool[((size_t)(b * 1024 + k)) * 128 + t];
    pq[t] = s * (1.0f / 65536.0f);
    __syncthreads();
    if (t < 64) {
        float a = b2[t];
        #pragma unroll 8
        for (int i = 0; i < 128; i++) a += w2[t * 128 + i] * pq[i];
        f[t] = a;
    }
    __syncthreads();
    if (t < 2) {
        float a = hb[t];
        #pragma unroll
        for (int o = 0; o < 64; o++) a += hw_[t * 64 + o] * f[o];
        float e = __expf(2.0f * a);
        out[b * 2 + t] = 1.0f - 2.0f / (e + 1.0f);
    }
}

extern "C" void kernel_launch(void* const* d_in, const int* in_sizes, int n_in,
                              void* d_out, int out_size) {
    const float* x    = (const float*)d_in[0];
    const float* lw   = (const float*)d_in[1];
    const float* lb   = (const float*)d_in[2];
    const float* w1r  = (const float*)d_in[3];
    const float* w1i  = (const float*)d_in[4];
    const float* w2r  = (const float*)d_in[5];
    const float* w2i  = (const float*)d_in[6];
    const float* skw  = (const float*)d_in[7];
    const float* skb  = (const float*)d_in[8];
    const float* pw1  = (const float*)d_in[9];
    const float* pb1  = (const float*)d_in[10];
    const float* pw2  = (const float*)d_in[11];
    const float* pb2  = (const float*)d_in[12];
    const float* hw_  = (const float*)d_in[13];
    const float* hb   = (const float*)d_in[14];
    float* out = (float*)d_out;

    k_tw<<<320, 256>>>();
    k_lift<<<BCHW / 256, 256>>>(x, lw, lb);
    for (int l = 0; l < Ln; l++) {
        int flip = l & 1;                    // input buffer: 0 -> g_v0
        k_xdft  <<<1024, 128>>>(flip);
        k_ydft  <<<512, 128>>>();
        k_mix   <<<512, 256>>>(w1r, w1i, w2r, w2i, l);
        k_hsynth<<<256, 256>>>();
        k_wsynth<<<4096, 256>>>(skw, skb, l, (l < Ln - 1) ? 1 : 0, flip);
    }
    // after 4 layers result is in g_v0
    k_proj<<<16384, 128>>>(pw1, pb1);
    k_head<<<Bn, 128>>>(pw2, pb2, hw_, hb, out);
}

// round 12
// speedup vs baseline: 1.9758x; 1.0175x over previous
#include <cuda_runtime.h>

// FNO with global head. B=16, C=16, H=W=256, L=4, modes 16x16.
// R12: R11 base (594us) + k_ydft converted to 3xTF32 error-compensated mma.

#define Bn 16
#define Cn 16
#define Hn 256
#define Wn 256
#define Ln 4
#define BCHW (Bn*Cn*Hn*Wn)

__device__ float g_v0[BCHW];                 // ping
__device__ float g_v1[BCHW];                 // pong
__device__ float g_a  [Bn*Cn*Hn*32];         // x-DFT result [row][2kx+ri]
__device__ float g_vftp[4*Bn*Cn*1024];       // ydft partials [ks][bc][m*32+kx*2+ri]
__device__ float g_mix[Bn*Cn*32*32];         // after channel mix
__device__ float g_gs [Bn*Cn*Hn*32];         // h-synth [bc*256+h][kx*2+ri]
__device__ float g_ehi[256*32];              // xdft E hi (tf32-rounded)
__device__ float g_elo[256*32];              // xdft E lo (residual)
__device__ float g_xc[16*256];               // wsynth cos[kx][w]
__device__ float g_xs[16*256];               // wsynth sin[kx][w]
__device__ float g_Thi[64*512];              // ydft T hi: [2m+ri][2h+p]
__device__ float g_Tlo[64*512];              // ydft T lo (residual)
__device__ float g_E3[512*64];               // hsynth E3: [2h+ro][2m+p]
__device__ float g_pool[Bn*1024*128];        // proj partial sums

__device__ __forceinline__ float gelu_t(float x) {
    const float k0 = 0.7978845608028654f;
    const float k1 = 0.044715f;
    float y = k0 * x * (1.0f + k1 * x * x);
    float th;
    asm("tanh.approx.f32 %0, %1;" : "=f"(th) : "f"(y));
    return 0.5f * x * (1.0f + th);
}

__device__ __forceinline__ unsigned f2tf32(float f) {
    unsigned u;
    asm("cvt.rna.tf32.f32 %0, %1;" : "=r"(u) : "f"(f));
    return u;
}

#define MMA_TF32(D, A, B0, B1)                                            \
    asm volatile(                                                          \
        "mma.sync.aligned.m16n8k8.row.col.f32.tf32.tf32.f32 "             \
        "{%0,%1,%2,%3}, {%4,%5,%6,%7}, {%8,%9}, {%0,%1,%2,%3};\n"         \
        : "+f"(D[0]), "+f"(D[1]), "+f"(D[2]), "+f"(D[3])                   \
        : "r"(A[0]), "r"(A[1]), "r"(A[2]), "r"(A[3]), "r"(B0), "r"(B1))

// ---------------- build all constant tables (grid 448) ----------------
__global__ void k_tw() {
    int j = blockIdx.x * 256 + threadIdx.x;
    if (j < 8192) {                                   // g_ehi / g_elo
        int w = j >> 5, c = j & 31;
        int kx = c >> 1, ri = c & 1;
        float ang = (float)((kx * w) & 255) / 128.0f;
        float e = ri ? -sinpif(ang) : cospif(ang);
        float hi = __uint_as_float(f2tf32(e));
        g_ehi[j] = hi;
        g_elo[j] = __uint_as_float(f2tf32(e - hi));
    } else if (j < 12288) {                           // g_xc
        int e = j - 8192;
        int kx = e >> 8, w = e & 255;
        g_xc[e] = cospif((float)((kx * w) & 255) / 128.0f);
    } else if (j < 16384) {                           // g_xs
        int e = j - 12288;
        int kx = e >> 8, w = e & 255;
        g_xs[e] = sinpif((float)((kx * w) & 255) / 128.0f);
    } else if (j < 49152) {                           // g_Thi [2m+ri][2h+p]
        int e = j - 16384;
        int row = e >> 9, col = e & 511;
        int m = row >> 1, ri = row & 1;
        int h = col >> 1, p = col & 1;
        int ky = (m < 16) ? m : (m + 224);
        float ang = (float)((ky * h) & 255) / 128.0f;
        float cy = cospif(ang), sy = sinpif(ang);
        float v = (ri == 0) ? (p == 0 ? cy : sy) : (p == 0 ? -sy : cy);
        g_Thi[e] = __uint_as_float(f2tf32(v));
    } else if (j < 81920) {                           // g_E3 [2h+ro][2m+p]
        int e = j - 49152;
        int row = e >> 6, col = e & 63;
        int h = row >> 1, ro = row & 1;
        int m = col >> 1, p = col & 1;
        int ky = (m < 16) ? m : (m + 224);
        float ang = (float)((ky * h) & 255) / 128.0f;
        float cy = cospif(ang), sy = sinpif(ang);
        g_E3[e] = (ro == 0) ? (p == 0 ? cy : -sy) : (p == 0 ? sy : cy);
    } else if (j < 114688) {                          // g_Tlo
        int e = j - 81920;
        int row = e >> 9, col = e & 511;
        int m = row >> 1, ri = row & 1;
        int h = col >> 1, p = col & 1;
        int ky = (m < 16) ? m : (m + 224);
        float ang = (float)((ky * h) & 255) / 128.0f;
        float cy = cospif(ang), sy = sinpif(ang);
        float v = (ri == 0) ? (p == 0 ? cy : sy) : (p == 0 ? -sy : cy);
        float hi = __uint_as_float(f2tf32(v));
        g_Tlo[e] = __uint_as_float(f2tf32(v - hi));
    }
}

// ---------------- lifting 1 -> 16 channels ----------------
__global__ void k_lift(const float* __restrict__ x,
                       const float* __restrict__ lw,
                       const float* __restrict__ lb) {
    int idx = blockIdx.x * blockDim.x + threadIdx.x;
    int w = idx & 255;
    int h = (idx >> 8) & 255;
    int c = (idx >> 16) & 15;
    int b = idx >> 20;
    float xv = x[(b << 16) | (h << 8) | w];
    g_v0[idx] = lw[c] * xv + lb[c];
}

// ---------------- x-DFT via 3xTF32 mma: C[64,32] = V[64,256] x E[256,32] --
__global__ void __launch_bounds__(128) k_xdft(int flip) {
    __shared__ float vs[64][68];      // V chunk; banks 4*gid+tig unique
    __shared__ float eh[64][40];      // Ehi chunk
    __shared__ float el[64][40];      // Elo chunk
    const float* __restrict__ vin = flip ? g_v1 : g_v0;
    int t = threadIdx.x;
    int lane = t & 31, warp = t >> 5;
    int gid = lane >> 2, tig = lane & 3;
    int rowbase = blockIdx.x * 64;
    const float* src = vin + (size_t)rowbase * 256;
    float d[4][4] = {};
    for (int kc = 0; kc < 4; kc++) {
        __syncthreads();
        for (int j = t; j < 1024; j += 128) {
            int r = j >> 4, q = j & 15;
            float4 v4 = *(const float4*)(src + r * 256 + kc * 64 + q * 4);
            vs[r][q * 4 + 0] = v4.x; vs[r][q * 4 + 1] = v4.y;
            vs[r][q * 4 + 2] = v4.z; vs[r][q * 4 + 3] = v4.w;
        }
        for (int j = t; j < 512; j += 128) {
            int k = j >> 3, q = j & 7;
            float4 h4 = *(const float4*)(g_ehi + (size_t)(kc * 64 + k) * 32 + q * 4);
            eh[k][q * 4 + 0] = h4.x; eh[k][q * 4 + 1] = h4.y;
            eh[k][q * 4 + 2] = h4.z; eh[k][q * 4 + 3] = h4.w;
            float4 l4 = *(const float4*)(g_elo + (size_t)(kc * 64 + k) * 32 + q * 4);
            el[k][q * 4 + 0] = l4.x; el[k][q * 4 + 1] = l4.y;
            el[k][q * 4 + 2] = l4.z; el[k][q * 4 + 3] = l4.w;
        }
        __syncthreads();
        #pragma unroll
        for (int ks = 0; ks < 8; ks++) {
            int kk = ks * 8;
            int m0 = warp * 16 + gid;
            float va[4];
            va[0] = vs[m0][kk + tig];     va[1] = vs[m0 + 8][kk + tig];
            va[2] = vs[m0][kk + tig + 4]; va[3] = vs[m0 + 8][kk + tig + 4];
            unsigned ah[4], al_[4];
            #pragma unroll
            for (int i = 0; i < 4; i++) {
                ah[i] = f2tf32(va[i]);
                al_[i] = f2tf32(va[i] - __uint_as_float(ah[i]));
            }
            #pragma unroll
            for (int nt = 0; nt < 4; nt++) {
                int n = nt * 8 + gid;
                unsigned bh0 = __float_as_uint(eh[kk + tig][n]);
                unsigned bh1 = __float_as_uint(eh[kk + tig + 4][n]);
                unsigned bl0 = __float_as_uint(el[kk + tig][n]);
                unsigned bl1 = __float_as_uint(el[kk + tig + 4][n]);
                MMA_TF32(d[nt], ah, bh0, bh1);
                MMA_TF32(d[nt], al_, bh0, bh1);
                MMA_TF32(d[nt], ah, bl0, bl1);
            }
        }
    }
    int m0 = rowbase + warp * 16 + gid;
    #pragma unroll
    for (int nt = 0; nt < 4; nt++) {
        int c0 = nt * 8 + 2 * tig;
        *(float2*)(g_a + (size_t)m0 * 32 + c0) = make_float2(d[nt][0], d[nt][1]);
        *(float2*)(g_a + (size_t)(m0 + 8) * 32 + c0) = make_float2(d[nt][2], d[nt][3]);
    }
}

// ---------------- y-DFT via 3xTF32 mma, K-split x4 ------------------------
// grid 512 = (bc/2)*4; block: C_part[64,32] = T[64, k:128] x A[k:128, 32].
// 128 thr = 4 warps (16-row m-tiles); 4 n-tiles; T hi/lo staged from tables,
// A (g_a) split on the fly.
__global__ void __launch_bounds__(128) k_ydft() {
    __shared__ float th[64][68];      // Thi chunk [row][k]; banks 4*gid+tig
    __shared__ float tl[64][68];      // Tlo chunk
    __shared__ float as[64][36];      // A chunk [k][col=bcq*16+kx]
    int t = threadIdx.x;
    int lane = t & 31, warp = t >> 5;
    int gid = lane >> 2, tig = lane & 3;
    int ks4 = blockIdx.x & 3;
    int bc0 = (blockIdx.x >> 2) * 2;
    float d[4][4] = {};
    for (int ci = 0; ci < 2; ci++) {
        int ch = ks4 * 2 + ci;
        int h0 = ch * 32, k0 = ch * 64;
        __syncthreads();
        for (int j = t; j < 1024; j += 128) {
            int row = j >> 4, q = j & 15;
            float4 h4 = *(const float4*)(g_Thi + (size_t)row * 512 + k0 + q * 4);
            th[row][q * 4 + 0] = h4.x; th[row][q * 4 + 1] = h4.y;
            th[row][q * 4 + 2] = h4.z; th[row][q * 4 + 3] = h4.w;
            float4 l4 = *(const float4*)(g_Tlo + (size_t)row * 512 + k0 + q * 4);
            tl[row][q * 4 + 0] = l4.x; tl[row][q * 4 + 1] = l4.y;
            tl[row][q * 4 + 2] = l4.z; tl[row][q * 4 + 3] = l4.w;
        }
        for (int j = t; j < 512; j += 128) {
            int bcq = j >> 8, rem = j & 255, hh = rem >> 3, q = rem & 7;
            float4 v4 = *(const float4*)(g_a + (size_t)((bc0 + bcq) * 256 + h0 + hh) * 32 + q * 4);
            int n0 = bcq * 16 + q * 2;
            as[2 * hh + 0][n0] = v4.x;     as[2 * hh + 1][n0] = v4.y;
            as[2 * hh + 0][n0 + 1] = v4.z; as[2 * hh + 1][n0 + 1] = v4.w;
        }
        __syncthreads();
        #pragma unroll
        for (int ks = 0; ks < 8; ks++) {
            int kk = ks * 8;
            int m0 = warp * 16 + gid;
            unsigned ah[4], al_[4];
            ah[0] = __float_as_uint(th[m0][kk + tig]);
            ah[1] = __float_as_uint(th[m0 + 8][kk + tig]);
            ah[2] = __float_as_uint(th[m0][kk + tig + 4]);
            ah[3] = __float_as_uint(th[m0 + 8][kk + tig + 4]);
            al_[0] = __float_as_uint(tl[m0][kk + tig]);
            al_[1] = __float_as_uint(tl[m0 + 8][kk + tig]);
            al_[2] = __float_as_uint(tl[m0][kk + tig + 4]);
            al_[3] = __float_as_uint(tl[m0 + 8][kk + tig + 4]);
            #pragma unroll
            for (int nt = 0; nt < 4; nt++) {
                int n = nt * 8 + gid;
                float b0 = as[kk + tig][n];
                float b1 = as[kk + tig + 4][n];
                unsigned bh0 = f2tf32(b0);
                unsigned bh1 = f2tf32(b1);
                unsigned bl0 = f2tf32(b0 - __uint_as_float(bh0));
                unsigned bl1 = f2tf32(b1 - __uint_as_float(bh1));
                MMA_TF32(d[nt], ah, bh0, bh1);
                MMA_TF32(d[nt], al_, bh0, bh1);
                MMA_TF32(d[nt], ah, bl0, bl1);
            }
        }
    }
    float* vout = g_vftp + (size_t)ks4 * (Bn * Cn * 1024);
    #pragma unroll
    for (int nt = 0; nt < 4; nt++) {
        #pragma unroll
        for (int e = 0; e < 4; e++) {
            int r = warp * 16 + gid + (e >= 2 ? 8 : 0);
            int c = nt * 8 + 2 * tig + (e & 1);
            int m = r >> 1, ri = r & 1;
            int bcq = c >> 4, kx = c & 15;
            vout[(bc0 + bcq) * 1024 + m * 32 + kx * 2 + ri] = d[nt][e];
        }
    }
}

// ---------------- per-mode 16x16 complex channel mixing (sums partials) --
__global__ void k_mix(const float* __restrict__ w1r, const float* __restrict__ w1i,
                      const float* __restrict__ w2r, const float* __restrict__ w2i,
                      int l) {
    int tid = blockIdx.x * blockDim.x + threadIdx.x;   // 131072
    int kx = tid & 15;
    int m = (tid >> 4) & 31;
    int o = (tid >> 9) & 15;
    int b = tid >> 13;
    int mm = m & 15;
    const float* wr = (m < 16) ? w1r : w2r;
    const float* wi = (m < 16) ? w1i : w2i;
    const int P = Bn * Cn * 1024;
    float accr = 0.f, acci = 0.f;
    #pragma unroll
    for (int i = 0; i < 16; i++) {
        int vidx = (b * 16 + i) * 1024 + m * 32 + kx * 2;
        float2 p0 = *(const float2*)(g_vftp + vidx);
        float2 p1 = *(const float2*)(g_vftp + P + vidx);
        float2 p2 = *(const float2*)(g_vftp + 2 * P + vidx);
        float2 p3 = *(const float2*)(g_vftp + 3 * P + vidx);
        float vr = (p0.x + p1.x) + (p2.x + p3.x);
        float vv = (p0.y + p1.y) + (p2.y + p3.y);
        int widx = (((l * 16 + i) * 16 + o) * 256) + mm * 16 + kx;
        float wrv = wr[widx], wiv = wi[widx];
        accr += vr * wrv - vv * wiv;
        acci += vr * wiv + vv * wrv;
    }
    int outi = (b * 16 + o) * 1024 + m * 32 + kx * 2;
    g_mix[outi + 0] = accr;
    g_mix[outi + 1] = acci;
}

// ---------------- h-synthesis GEMM per bc: C[512,16] = E3[512,64] x M ----
__global__ void __launch_bounds__(256) k_hsynth() {
    __shared__ float mixT[16][68];    // [kx][2m+p]
    int t = threadIdx.x;
    int bc = blockIdx.x;
    {
        float4 v4 = *(const float4*)(g_mix + (size_t)bc * 1024 + t * 4);
        int i4 = t * 4;
        #pragma unroll
        for (int e = 0; e < 4; e++) {
            int idx = i4 + e;
            int m = idx >> 5, rem = idx & 31, kx = rem >> 1, p = rem & 1;
            float val = (e == 0) ? v4.x : (e == 1) ? v4.y : (e == 2) ? v4.z : v4.w;
            mixT[kx][2 * m + p] = val;
        }
    }
    __syncthreads();
    int rg = t >> 3, cg = t & 7;
    float acc[16][2] = {};
    for (int ks = 0; ks < 64; ks += 4) {
        float4 bf0 = *(const float4*)&mixT[cg * 2 + 0][ks];
        float4 bf1 = *(const float4*)&mixT[cg * 2 + 1][ks];
        #pragma unroll
        for (int i = 0; i < 16; i++) {
            float4 af = *(const float4*)(g_E3 + (size_t)(32 * i + rg) * 64 + ks);
            acc[i][0] += af.x * bf0.x + af.y * bf0.y + af.z * bf0.z + af.w * bf0.w;
            acc[i][1] += af.x * bf1.x + af.y * bf1.y + af.z * bf1.z + af.w * bf1.w;
        }
    }
    #pragma unroll
    for (int i = 0; i < 16; i++) {
        int r = 32 * i + rg, h = r >> 1, ro = r & 1;
        #pragma unroll
        for (int jj = 0; jj < 2; jj++) {
            int kx = cg * 2 + jj;
            float sc = (kx == 0) ? (1.0f / 65536.0f) : (2.0f / 65536.0f);
            g_gs[(size_t)(bc * 256 + h) * 32 + kx * 2 + ro] = acc[i][jj] * sc;
        }
    }
}

// ---------------- fused w-synth + skip + gelu via tf32 mma.sync ----------
__global__ void __launch_bounds__(256) k_wsynth(const float* __restrict__ skw,
                         const float* __restrict__ skb,
                         int l, int act, int flip) {
    __shared__ float vs[16][260];     // stride 260: conflict-free quad reads
    __shared__ float ms[16][52];      // [o][0:16 skw | 16:32 gr | 32:48 -gi]
    __shared__ float sb[16];
    const float* __restrict__ vin = flip ? g_v1 : g_v0;
    float* __restrict__ vout = flip ? g_v0 : g_v1;
    int t = threadIdx.x;
    int lane = t & 31, warp = t >> 5;
    int b = blockIdx.x >> 8, h = blockIdx.x & 255;
    for (int j = t; j < 1024; j += 256) {
        int c = j >> 6, q = j & 63;
        float4 v4 = *(const float4*)(vin + ((size_t)(b * 16 + c) * 256 + h) * 256 + q * 4);
        vs[c][q * 4 + 0] = v4.x; vs[c][q * 4 + 1] = v4.y;
        vs[c][q * 4 + 2] = v4.z; vs[c][q * 4 + 3] = v4.w;
    }
    {
        int c = t >> 4, k = t & 15;
        ms[c][k] = skw[l * 256 + c * 16 + k];
        int base = ((size_t)(b * 16 + c) * 256 + h) * 32 + k * 2;
        ms[c][16 + k] = g_gs[base];
        ms[c][32 + k] = -g_gs[base + 1];
        if (t < 16) sb[t] = skb[l * 16 + t];
    }
    __syncthreads();
    int gid = lane >> 2, tig = lane & 3;
    unsigned a[6][4];
    #pragma unroll
    for (int ks = 0; ks < 6; ks++) {
        int c0 = ks * 8 + tig;
        a[ks][0] = f2tf32(ms[gid][c0]);
        a[ks][1] = f2tf32(ms[gid + 8][c0]);
        a[ks][2] = f2tf32(ms[gid][c0 + 4]);
        a[ks][3] = f2tf32(ms[gid + 8][c0 + 4]);
    }
    float bias0 = sb[gid], bias1 = sb[gid + 8];
    float* out0 = vout + ((size_t)(b * 16 + gid) * 256 + h) * 256;
    float* out1 = vout + ((size_t)(b * 16 + gid + 8) * 256 + h) * 256;
    #pragma unroll
    for (int nt = 0; nt < 4; nt++) {
        int n = warp * 32 + nt * 8 + gid;
        unsigned bf[6][2];
        bf[0][0] = f2tf32(vs[tig][n]);        bf[0][1] = f2tf32(vs[tig + 4][n]);
        bf[1][0] = f2tf32(vs[8 + tig][n]);    bf[1][1] = f2tf32(vs[12 + tig][n]);
        bf[2][0] = f2tf32(g_xc[tig * 256 + n]);
        bf[2][1] = f2tf32(g_xc[(tig + 4) * 256 + n]);
        bf[3][0] = f2tf32(g_xc[(8 + tig) * 256 + n]);
        bf[3][1] = f2tf32(g_xc[(12 + tig) * 256 + n]);
        bf[4][0] = f2tf32(g_xs[tig * 256 + n]);
        bf[4][1] = f2tf32(g_xs[(tig + 4) * 256 + n]);
        bf[5][0] = f2tf32(g_xs[(8 + tig) * 256 + n]);
        bf[5][1] = f2tf32(g_xs[(12 + tig) * 256 + n]);
        float d0 = 0.f, d1 = 0.f, d2 = 0.f, d3 = 0.f;
        #pragma unroll
        for (int ks = 0; ks < 6; ks++) {
            asm volatile(
                "mma.sync.aligned.m16n8k8.row.col.f32.tf32.tf32.f32 "
                "{%0,%1,%2,%3}, {%4,%5,%6,%7}, {%8,%9}, {%0,%1,%2,%3};\n"
                : "+f"(d0), "+f"(d1), "+f"(d2), "+f"(d3)
                : "r"(a[ks][0]), "r"(a[ks][1]), "r"(a[ks][2]), "r"(a[ks][3]),
                  "r"(bf[ks][0]), "r"(bf[ks][1]));
        }
        d0 += bias0; d1 += bias0; d2 += bias1; d3 += bias1;
        if (act) {
            d0 = gelu_t(d0); d1 = gelu_t(d1);
            d2 = gelu_t(d2); d3 = gelu_t(d3);
        }
        int w = warp * 32 + nt * 8 + 2 * tig;
        *(float2*)(out0 + w) = make_float2(d0, d1);
        *(float2*)(out1 + w) = make_float2(d2, d3);
    }
}

// ---------------- proj1 (16->128) + gelu + pooling via tf32 mma.sync -----
__global__ void __launch_bounds__(128) k_proj(const float* __restrict__ w1,
                                              const float* __restrict__ b1) {
    __shared__ float vs[16][72];          // stride 72: conflict-free B reads
    int t = threadIdx.x;
    int lane = t & 31, warp = t >> 5;
    int blk = blockIdx.x;                 // b*1024 + h*4 + wc
    int wc = blk & 3, h = (blk >> 2) & 255, b = blk >> 10;
    const float* vrow = g_v0 + ((size_t)(b * 16) * 256 + h) * 256 + wc * 64;
    for (int j = t; j < 256; j += 128) {  // 256 float4 = 16ch x 64px
        int c = j >> 4, p4 = j & 15;
        float4 v4 = ((const float4*)(vrow + (size_t)c * 65536))[p4];
        vs[c][p4 * 4 + 0] = v4.x; vs[c][p4 * 4 + 1] = v4.y;
        vs[c][p4 * 4 + 2] = v4.z; vs[c][p4 * 4 + 3] = v4.w;
    }
    int gid = lane >> 2, tig = lane & 3;  // groupID, threadID_in_group
    int m_base = warp * 32;
    unsigned a[2][2][4];
    float bb[2][2];
    #pragma unroll
    for (int mt = 0; mt < 2; mt++) {
        int r_lo = m_base + mt * 16 + gid;
        bb[mt][0] = b1[r_lo];
        bb[mt][1] = b1[r_lo + 8];
        #pragma unroll
        for (int ks = 0; ks < 2; ks++) {
            int c_lo = ks * 8 + tig;
            a[mt][ks][0] = f2tf32(w1[r_lo * 16 + c_lo]);
            a[mt][ks][1] = f2tf32(w1[(r_lo + 8) * 16 + c_lo]);
            a[mt][ks][2] = f2tf32(w1[r_lo * 16 + c_lo + 4]);
            a[mt][ks][3] = f2tf32(w1[(r_lo + 8) * 16 + c_lo + 4]);
        }
    }
    __syncthreads();
    float s[2][2] = {};                    // pooled sums per (mt, row-half)
    #pragma unroll
    for (int nt = 0; nt < 8; nt++) {
        int n = nt * 8 + gid;
        unsigned bfr[2][2];
        #pragma unroll
        for (int ks = 0; ks < 2; ks++) {
            bfr[ks][0] = f2tf32(vs[ks * 8 + tig][n]);
            bfr[ks][1] = f2tf32(vs[ks * 8 + tig + 4][n]);
        }
        #pragma unroll
        for (int mt = 0; mt < 2; mt++) {
            float d0 = 0.f, d1 = 0.f, d2 = 0.f, d3 = 0.f;
            #pragma unroll
            for (int ks = 0; ks < 2; ks++) {
                asm volatile(
                    "mma.sync.aligned.m16n8k8.row.col.f32.tf32.tf32.f32 "
                    "{%0,%1,%2,%3}, {%4,%5,%6,%7}, {%8,%9}, {%0,%1,%2,%3};\n"
                    : "+f"(d0), "+f"(d1), "+f"(d2), "+f"(d3)
                    : "r"(a[mt][ks][0]), "r"(a[mt][ks][1]),
                      "r"(a[mt][ks][2]), "r"(a[mt][ks][3]),
                      "r"(bfr[ks][0]), "r"(bfr[ks][1]));
            }
            s[mt][0] += gelu_t(d0 + bb[mt][0]) + gelu_t(d1 + bb[mt][0]);
            s[mt][1] += gelu_t(d2 + bb[mt][1]) + gelu_t(d3 + bb[mt][1]);
        }
    }
    #pragma unroll
    for (int mt = 0; mt < 2; mt++) {
        #pragma unroll
        for (int hh = 0; hh < 2; hh++) {
            float v = s[mt][hh];
            v += __shfl_xor_sync(0xFFFFFFFFu, v, 1);
            v += __shfl_xor_sync(0xFFFFFFFFu, v, 2);
            s[mt][hh] = v;
        }
    }
    if (tig == 0) {
        float* dst = g_pool + (size_t)blk * 128;
        #pragma unroll
        for (int mt = 0; mt < 2; mt++) {
            dst[m_base + mt * 16 + gid]     = s[mt][0];
            dst[m_base + mt * 16 + gid + 8] = s[mt][1];
        }
    }
}

// ---------------- final reduce + proj2 on pooled vector + head -----------
__global__ void k_head(const float* __restrict__ w2, const float* __restrict__ b2,
                       const float* __restrict__ hw_, const float* __restrict__ hb,
                       float* __restrict__ out) {
    __shared__ float pq[128];
    __shared__ float f[64];
    int b = blockIdx.x, t = threadIdx.x;
    float s = 0.f;
    for (int k = 0; k < 1024; k++)
        s += g_pool[((size_t)(b * 1024 + k)) * 128 + t];
    pq[t] = s * (1.0f / 65536.0f);
    __syncthreads();
    if (t < 64) {
        float a = b2[t];
        #pragma unroll 8
        for (int i = 0; i < 128; i++) a += w2[t * 128 + i] * pq[i];
        f[t] = a;
    }
    __syncthreads();
    if (t < 2) {
        float a = hb[t];
        #pragma unroll
        for (int o = 0; o < 64; o++) a += hw_[t * 64 + o] * f[o];
        float e = __expf(2.0f * a);
        out[b * 2 + t] = 1.0f - 2.0f / (e + 1.0f);
    }
}

extern "C" void kernel_launch(void* const* d_in, const int* in_sizes, int n_in,
                              void* d_out, int out_size) {
    const float* x    = (const float*)d_in[0];
    const float* lw   = (const float*)d_in[1];
    const float* lb   = (const float*)d_in[2];
    const float* w1r  = (const float*)d_in[3];
    const float* w1i  = (const float*)d_in[4];
    const float* w2r  = (const float*)d_in[5];
    const float* w2i  = (const float*)d_in[6];
    const float* skw  = (const float*)d_in[7];
    const float* skb  = (const float*)d_in[8];
    const float* pw1  = (const float*)d_in[9];
    const float* pb1  = (const float*)d_in[10];
    const float* pw2  = (const float*)d_in[11];
    const float* pb2  = (const float*)d_in[12];
    const float* hw_  = (const float*)d_in[13];
    const float* hb   = (const float*)d_in[14];
    float* out = (float*)d_out;

    k_tw<<<448, 256>>>();
    k_lift<<<BCHW / 256, 256>>>(x, lw, lb);
    for (int l = 0; l < Ln; l++) {
        int flip = l & 1;                    // input buffer: 0 -> g_v0
        k_xdft  <<<1024, 128>>>(flip);
        k_ydft  <<<512, 128>>>();
        k_mix   <<<512, 256>>>(w1r, w1i, w2r, w2i, l);
        k_hsynth<<<256, 256>>>();
        k_wsynth<<<4096, 256>>>(skw, skb, l, (l < Ln - 1) ? 1 : 0, flip);
    }
    // after 4 layers result is in g_v0
    k_proj<<<16384, 128>>>(pw1, pb1);
    k_head<<<Bn, 128>>>(pw2, pb2, hw_, hb, out);
}

// round 13
// speedup vs baseline: 2.0686x; 1.0469x over previous
#include <cuda_runtime.h>

// FNO with global head. B=16, C=16, H=W=256, L=4, modes 16x16.
// R13: R12 base (583us) + proj1+gelu+pool fused into wsynth layer 3.

#define Bn 16
#define Cn 16
#define Hn 256
#define Wn 256
#define Ln 4
#define BCHW (Bn*Cn*Hn*Wn)

__device__ float g_v0[BCHW];                 // ping
__device__ float g_v1[BCHW];                 // pong
__device__ float g_a  [Bn*Cn*Hn*32];         // x-DFT result [row][2kx+ri]
__device__ float g_vftp[4*Bn*Cn*1024];       // ydft partials [ks][bc][m*32+kx*2+ri]
__device__ float g_mix[Bn*Cn*32*32];         // after channel mix
__device__ float g_gs [Bn*Cn*Hn*32];         // h-synth [bc*256+h][kx*2+ri]
__device__ float g_ehi[256*32];              // xdft E hi (tf32-rounded)
__device__ float g_elo[256*32];              // xdft E lo (residual)
__device__ float g_xc[16*256];               // wsynth cos[kx][w]
__device__ float g_xs[16*256];               // wsynth sin[kx][w]
__device__ float g_Thi[64*512];              // ydft T hi: [2m+ri][2h+p]
__device__ float g_Tlo[64*512];              // ydft T lo (residual)
__device__ float g_E3[512*64];               // hsynth E3: [2h+ro][2m+p]
__device__ float g_pool[Bn*256*128];         // proj partial sums (per b,h)

__device__ __forceinline__ float gelu_t(float x) {
    const float k0 = 0.7978845608028654f;
    const float k1 = 0.044715f;
    float y = k0 * x * (1.0f + k1 * x * x);
    float th;
    asm("tanh.approx.f32 %0, %1;" : "=f"(th) : "f"(y));
    return 0.5f * x * (1.0f + th);
}

__device__ __forceinline__ unsigned f2tf32(float f) {
    unsigned u;
    asm("cvt.rna.tf32.f32 %0, %1;" : "=r"(u) : "f"(f));
    return u;
}

#define MMA_TF32(D, A, B0, B1)                                            \
    asm volatile(                                                          \
        "mma.sync.aligned.m16n8k8.row.col.f32.tf32.tf32.f32 "             \
        "{%0,%1,%2,%3}, {%4,%5,%6,%7}, {%8,%9}, {%0,%1,%2,%3};\n"         \
        : "+f"(D[0]), "+f"(D[1]), "+f"(D[2]), "+f"(D[3])                   \
        : "r"(A[0]), "r"(A[1]), "r"(A[2]), "r"(A[3]), "r"(B0), "r"(B1))

// ---------------- build all constant tables (grid 448) ----------------
__global__ void k_tw() {
    int j = blockIdx.x * 256 + threadIdx.x;
    if (j < 8192) {                                   // g_ehi / g_elo
        int w = j >> 5, c = j & 31;
        int kx = c >> 1, ri = c & 1;
        float ang = (float)((kx * w) & 255) / 128.0f;
        float e = ri ? -sinpif(ang) : cospif(ang);
        float hi = __uint_as_float(f2tf32(e));
        g_ehi[j] = hi;
        g_elo[j] = __uint_as_float(f2tf32(e - hi));
    } else if (j < 12288) {                           // g_xc
        int e = j - 8192;
        int kx = e >> 8, w = e & 255;
        g_xc[e] = cospif((float)((kx * w) & 255) / 128.0f);
    } else if (j < 16384) {                           // g_xs
        int e = j - 12288;
        int kx = e >> 8, w = e & 255;
        g_xs[e] = sinpif((float)((kx * w) & 255) / 128.0f);
    } else if (j < 49152) {                           // g_Thi [2m+ri][2h+p]
        int e = j - 16384;
        int row = e >> 9, col = e & 511;
        int m = row >> 1, ri = row & 1;
        int h = col >> 1, p = col & 1;
        int ky = (m < 16) ? m : (m + 224);
        float ang = (float)((ky * h) & 255) / 128.0f;
        float cy = cospif(ang), sy = sinpif(ang);
        float v = (ri == 0) ? (p == 0 ? cy : sy) : (p == 0 ? -sy : cy);
        g_Thi[e] = __uint_as_float(f2tf32(v));
    } else if (j < 81920) {                           // g_E3 [2h+ro][2m+p]
        int e = j - 49152;
        int row = e >> 6, col = e & 63;
        int h = row >> 1, ro = row & 1;
        int m = col >> 1, p = col & 1;
        int ky = (m < 16) ? m : (m + 224);
        float ang = (float)((ky * h) & 255) / 128.0f;
        float cy = cospif(ang), sy = sinpif(ang);
        g_E3[e] = (ro == 0) ? (p == 0 ? cy : -sy) : (p == 0 ? sy : cy);
    } else if (j < 114688) {                          // g_Tlo
        int e = j - 81920;
        int row = e >> 9, col = e & 511;
        int m = row >> 1, ri = row & 1;
        int h = col >> 1, p = col & 1;
        int ky = (m < 16) ? m : (m + 224);
        float ang = (float)((ky * h) & 255) / 128.0f;
        float cy = cospif(ang), sy = sinpif(ang);
        float v = (ri == 0) ? (p == 0 ? cy : sy) : (p == 0 ? -sy : cy);
        float hi = __uint_as_float(f2tf32(v));
        g_Tlo[e] = __uint_as_float(f2tf32(v - hi));
    }
}

// ---------------- lifting 1 -> 16 channels ----------------
__global__ void k_lift(const float* __restrict__ x,
                       const float* __restrict__ lw,
                       const float* __restrict__ lb) {
    int idx = blockIdx.x * blockDim.x + threadIdx.x;
    int w = idx & 255;
    int h = (idx >> 8) & 255;
    int c = (idx >> 16) & 15;
    int b = idx >> 20;
    float xv = x[(b << 16) | (h << 8) | w];
    g_v0[idx] = lw[c] * xv + lb[c];
}

// ---------------- x-DFT via 3xTF32 mma: C[64,32] = V[64,256] x E[256,32] --
__global__ void __launch_bounds__(128) k_xdft(int flip) {
    __shared__ float vs[64][68];      // V chunk; banks 4*gid+tig unique
    __shared__ float eh[64][40];      // Ehi chunk
    __shared__ float el[64][40];      // Elo chunk
    const float* __restrict__ vin = flip ? g_v1 : g_v0;
    int t = threadIdx.x;
    int lane = t & 31, warp = t >> 5;
    int gid = lane >> 2, tig = lane & 3;
    int rowbase = blockIdx.x * 64;
    const float* src = vin + (size_t)rowbase * 256;
    float d[4][4] = {};
    for (int kc = 0; kc < 4; kc++) {
        __syncthreads();
        for (int j = t; j < 1024; j += 128) {
            int r = j >> 4, q = j & 15;
            float4 v4 = *(const float4*)(src + r * 256 + kc * 64 + q * 4);
            vs[r][q * 4 + 0] = v4.x; vs[r][q * 4 + 1] = v4.y;
            vs[r][q * 4 + 2] = v4.z; vs[r][q * 4 + 3] = v4.w;
        }
        for (int j = t; j < 512; j += 128) {
            int k = j >> 3, q = j & 7;
            float4 h4 = *(const float4*)(g_ehi + (size_t)(kc * 64 + k) * 32 + q * 4);
            eh[k][q * 4 + 0] = h4.x; eh[k][q * 4 + 1] = h4.y;
            eh[k][q * 4 + 2] = h4.z; eh[k][q * 4 + 3] = h4.w;
            float4 l4 = *(const float4*)(g_elo + (size_t)(kc * 64 + k) * 32 + q * 4);
            el[k][q * 4 + 0] = l4.x; el[k][q * 4 + 1] = l4.y;
            el[k][q * 4 + 2] = l4.z; el[k][q * 4 + 3] = l4.w;
        }
        __syncthreads();
        #pragma unroll
        for (int ks = 0; ks < 8; ks++) {
            int kk = ks * 8;
            int m0 = warp * 16 + gid;
            float va[4];
            va[0] = vs[m0][kk + tig];     va[1] = vs[m0 + 8][kk + tig];
            va[2] = vs[m0][kk + tig + 4]; va[3] = vs[m0 + 8][kk + tig + 4];
            unsigned ah[4], al_[4];
            #pragma unroll
            for (int i = 0; i < 4; i++) {
                ah[i] = f2tf32(va[i]);
                al_[i] = f2tf32(va[i] - __uint_as_float(ah[i]));
            }
            #pragma unroll
            for (int nt = 0; nt < 4; nt++) {
                int n = nt * 8 + gid;
                unsigned bh0 = __float_as_uint(eh[kk + tig][n]);
                unsigned bh1 = __float_as_uint(eh[kk + tig + 4][n]);
                unsigned bl0 = __float_as_uint(el[kk + tig][n]);
                unsigned bl1 = __float_as_uint(el[kk + tig + 4][n]);
                MMA_TF32(d[nt], ah, bh0, bh1);
                MMA_TF32(d[nt], al_, bh0, bh1);
                MMA_TF32(d[nt], ah, bl0, bl1);
            }
        }
    }
    int m0 = rowbase + warp * 16 + gid;
    #pragma unroll
    for (int nt = 0; nt < 4; nt++) {
        int c0 = nt * 8 + 2 * tig;
        *(float2*)(g_a + (size_t)m0 * 32 + c0) = make_float2(d[nt][0], d[nt][1]);
        *(float2*)(g_a + (size_t)(m0 + 8) * 32 + c0) = make_float2(d[nt][2], d[nt][3]);
    }
}

// ---------------- y-DFT via 3xTF32 mma, K-split x4 ------------------------
__global__ void __launch_bounds__(128) k_ydft() {
    __shared__ float th[64][68];      // Thi chunk [row][k]
    __shared__ float tl[64][68];      // Tlo chunk
    __shared__ float as[64][36];      // A chunk [k][col=bcq*16+kx]
    int t = threadIdx.x;
    int lane = t & 31, warp = t >> 5;
    int gid = lane >> 2, tig = lane & 3;
    int ks4 = blockIdx.x & 3;
    int bc0 = (blockIdx.x >> 2) * 2;
    float d[4][4] = {};
    for (int ci = 0; ci < 2; ci++) {
        int ch = ks4 * 2 + ci;
        int h0 = ch * 32, k0 = ch * 64;
        __syncthreads();
        for (int j = t; j < 1024; j += 128) {
            int row = j >> 4, q = j & 15;
            float4 h4 = *(const float4*)(g_Thi + (size_t)row * 512 + k0 + q * 4);
            th[row][q * 4 + 0] = h4.x; th[row][q * 4 + 1] = h4.y;
            th[row][q * 4 + 2] = h4.z; th[row][q * 4 + 3] = h4.w;
            float4 l4 = *(const float4*)(g_Tlo + (size_t)row * 512 + k0 + q * 4);
            tl[row][q * 4 + 0] = l4.x; tl[row][q * 4 + 1] = l4.y;
            tl[row][q * 4 + 2] = l4.z; tl[row][q * 4 + 3] = l4.w;
        }
        for (int j = t; j < 512; j += 128) {
            int bcq = j >> 8, rem = j & 255, hh = rem >> 3, q = rem & 7;
            float4 v4 = *(const float4*)(g_a + (size_t)((bc0 + bcq) * 256 + h0 + hh) * 32 + q * 4);
            int n0 = bcq * 16 + q * 2;
            as[2 * hh + 0][n0] = v4.x;     as[2 * hh + 1][n0] = v4.y;
            as[2 * hh + 0][n0 + 1] = v4.z; as[2 * hh + 1][n0 + 1] = v4.w;
        }
        __syncthreads();
        #pragma unroll
        for (int ks = 0; ks < 8; ks++) {
            int kk = ks * 8;
            int m0 = warp * 16 + gid;
            unsigned ah[4], al_[4];
            ah[0] = __float_as_uint(th[m0][kk + tig]);
            ah[1] = __float_as_uint(th[m0 + 8][kk + tig]);
            ah[2] = __float_as_uint(th[m0][kk + tig + 4]);
            ah[3] = __float_as_uint(th[m0 + 8][kk + tig + 4]);
            al_[0] = __float_as_uint(tl[m0][kk + tig]);
            al_[1] = __float_as_uint(tl[m0 + 8][kk + tig]);
            al_[2] = __float_as_uint(tl[m0][kk + tig + 4]);
            al_[3] = __float_as_uint(tl[m0 + 8][kk + tig + 4]);
            #pragma unroll
            for (int nt = 0; nt < 4; nt++) {
                int n = nt * 8 + gid;
                float b0 = as[kk + tig][n];
                float b1 = as[kk + tig + 4][n];
                unsigned bh0 = f2tf32(b0);
                unsigned bh1 = f2tf32(b1);
                unsigned bl0 = f2tf32(b0 - __uint_as_float(bh0));
                unsigned bl1 = f2tf32(b1 - __uint_as_float(bh1));
                MMA_TF32(d[nt], ah, bh0, bh1);
                MMA_TF32(d[nt], al_, bh0, bh1);
                MMA_TF32(d[nt], ah, bl0, bl1);
            }
        }
    }
    float* vout = g_vftp + (size_t)ks4 * (Bn * Cn * 1024);
    #pragma unroll
    for (int nt = 0; nt < 4; nt++) {
        #pragma unroll
        for (int e = 0; e < 4; e++) {
            int r = warp * 16 + gid + (e >= 2 ? 8 : 0);
            int c = nt * 8 + 2 * tig + (e & 1);
            int m = r >> 1, ri = r & 1;
            int bcq = c >> 4, kx = c & 15;
            vout[(bc0 + bcq) * 1024 + m * 32 + kx * 2 + ri] = d[nt][e];
        }
    }
}

// ---------------- per-mode 16x16 complex channel mixing (sums partials) --
__global__ void k_mix(const float* __restrict__ w1r, const float* __restrict__ w1i,
                      const float* __restrict__ w2r, const float* __restrict__ w2i,
                      int l) {
    int tid = blockIdx.x * blockDim.x + threadIdx.x;   // 131072
    int kx = tid & 15;
    int m = (tid >> 4) & 31;
    int o = (tid >> 9) & 15;
    int b = tid >> 13;
    int mm = m & 15;
    const float* wr = (m < 16) ? w1r : w2r;
    const float* wi = (m < 16) ? w1i : w2i;
    const int P = Bn * Cn * 1024;
    float accr = 0.f, acci = 0.f;
    #pragma unroll
    for (int i = 0; i < 16; i++) {
        int vidx = (b * 16 + i) * 1024 + m * 32 + kx * 2;
        float2 p0 = *(const float2*)(g_vftp + vidx);
        float2 p1 = *(const float2*)(g_vftp + P + vidx);
        float2 p2 = *(const float2*)(g_vftp + 2 * P + vidx);
        float2 p3 = *(const float2*)(g_vftp + 3 * P + vidx);
        float vr = (p0.x + p1.x) + (p2.x + p3.x);
        float vv = (p0.y + p1.y) + (p2.y + p3.y);
        int widx = (((l * 16 + i) * 16 + o) * 256) + mm * 16 + kx;
        float wrv = wr[widx], wiv = wi[widx];
        accr += vr * wrv - vv * wiv;
        acci += vr * wiv + vv * wrv;
    }
    int outi = (b * 16 + o) * 1024 + m * 32 + kx * 2;
    g_mix[outi + 0] = accr;
    g_mix[outi + 1] = acci;
}

// ---------------- h-synthesis GEMM per bc: C[512,16] = E3[512,64] x M ----
__global__ void __launch_bounds__(256) k_hsynth() {
    __shared__ float mixT[16][68];    // [kx][2m+p]
    int t = threadIdx.x;
    int bc = blockIdx.x;
    {
        float4 v4 = *(const float4*)(g_mix + (size_t)bc * 1024 + t * 4);
        int i4 = t * 4;
        #pragma unroll
        for (int e = 0; e < 4; e++) {
            int idx = i4 + e;
            int m = idx >> 5, rem = idx & 31, kx = rem >> 1, p = rem & 1;
            float val = (e == 0) ? v4.x : (e == 1) ? v4.y : (e == 2) ? v4.z : v4.w;
            mixT[kx][2 * m + p] = val;
        }
    }
    __syncthreads();
    int rg = t >> 3, cg = t & 7;
    float acc[16][2] = {};
    for (int ks = 0; ks < 64; ks += 4) {
        float4 bf0 = *(const float4*)&mixT[cg * 2 + 0][ks];
        float4 bf1 = *(const float4*)&mixT[cg * 2 + 1][ks];
        #pragma unroll
        for (int i = 0; i < 16; i++) {
            float4 af = *(const float4*)(g_E3 + (size_t)(32 * i + rg) * 64 + ks);
            acc[i][0] += af.x * bf0.x + af.y * bf0.y + af.z * bf0.z + af.w * bf0.w;
            acc[i][1] += af.x * bf1.x + af.y * bf1.y + af.z * bf1.z + af.w * bf1.w;
        }
    }
    #pragma unroll
    for (int i = 0; i < 16; i++) {
        int r = 32 * i + rg, h = r >> 1, ro = r & 1;
        #pragma unroll
        for (int jj = 0; jj < 2; jj++) {
            int kx = cg * 2 + jj;
            float sc = (kx == 0) ? (1.0f / 65536.0f) : (2.0f / 65536.0f);
            g_gs[(size_t)(bc * 256 + h) * 32 + kx * 2 + ro] = acc[i][jj] * sc;
        }
    }
}

// ---------------- fused w-synth + skip (+ gelu | + proj1+gelu+pool) ------
// Block per (b,h), 256 thr = 8 warps. OUT[16,256] = A[16,48] x B[48,256].
// mode 1: gelu + store to vout.  mode 0 (last layer): no gelu on v; run
// proj1 (128x16) on OUT in-block, gelu, pool over 256 pixels -> g_pool.
__global__ void __launch_bounds__(256) k_wsynth(const float* __restrict__ skw,
                         const float* __restrict__ skb,
                         const float* __restrict__ pw1,
                         const float* __restrict__ pb1,
                         int l, int mode, int flip) {
    __shared__ float vs[16][260];
    __shared__ float ms[16][52];      // [o][0:16 skw | 16:32 gr | 32:48 -gi]
    __shared__ float sb[16];
    __shared__ float outs[16][264];   // staged OUT for fused proj (mode 0)
    const float* __restrict__ vin = flip ? g_v1 : g_v0;
    float* __restrict__ vout = flip ? g_v0 : g_v1;
    int t = threadIdx.x;
    int lane = t & 31, warp = t >> 5;
    int b = blockIdx.x >> 8, h = blockIdx.x & 255;
    for (int j = t; j < 1024; j += 256) {
        int c = j >> 6, q = j & 63;
        float4 v4 = *(const float4*)(vin + ((size_t)(b * 16 + c) * 256 + h) * 256 + q * 4);
        vs[c][q * 4 + 0] = v4.x; vs[c][q * 4 + 1] = v4.y;
        vs[c][q * 4 + 2] = v4.z; vs[c][q * 4 + 3] = v4.w;
    }
    {
        int c = t >> 4, k = t & 15;
        ms[c][k] = skw[l * 256 + c * 16 + k];
        int base = ((size_t)(b * 16 + c) * 256 + h) * 32 + k * 2;
        ms[c][16 + k] = g_gs[base];
        ms[c][32 + k] = -g_gs[base + 1];
        if (t < 16) sb[t] = skb[l * 16 + t];
    }
    __syncthreads();
    int gid = lane >> 2, tig = lane & 3;
    unsigned a[6][4];
    #pragma unroll
    for (int ks = 0; ks < 6; ks++) {
        int c0 = ks * 8 + tig;
        a[ks][0] = f2tf32(ms[gid][c0]);
        a[ks][1] = f2tf32(ms[gid + 8][c0]);
        a[ks][2] = f2tf32(ms[gid][c0 + 4]);
        a[ks][3] = f2tf32(ms[gid + 8][c0 + 4]);
    }
    float bias0 = sb[gid], bias1 = sb[gid + 8];
    float* out0 = vout + ((size_t)(b * 16 + gid) * 256 + h) * 256;
    float* out1 = vout + ((size_t)(b * 16 + gid + 8) * 256 + h) * 256;
    #pragma unroll
    for (int nt = 0; nt < 4; nt++) {
        int n = warp * 32 + nt * 8 + gid;
        unsigned bf[6][2];
        bf[0][0] = f2tf32(vs[tig][n]);        bf[0][1] = f2tf32(vs[tig + 4][n]);
        bf[1][0] = f2tf32(vs[8 + tig][n]);    bf[1][1] = f2tf32(vs[12 + tig][n]);
        bf[2][0] = f2tf32(g_xc[tig * 256 + n]);
        bf[2][1] = f2tf32(g_xc[(tig + 4) * 256 + n]);
        bf[3][0] = f2tf32(g_xc[(8 + tig) * 256 + n]);
        bf[3][1] = f2tf32(g_xc[(12 + tig) * 256 + n]);
        bf[4][0] = f2tf32(g_xs[tig * 256 + n]);
        bf[4][1] = f2tf32(g_xs[(tig + 4) * 256 + n]);
        bf[5][0] = f2tf32(g_xs[(8 + tig) * 256 + n]);
        bf[5][1] = f2tf32(g_xs[(12 + tig) * 256 + n]);
        float d0 = 0.f, d1 = 0.f, d2 = 0.f, d3 = 0.f;
        #pragma unroll
        for (int ks = 0; ks < 6; ks++) {
            asm volatile(
                "mma.sync.aligned.m16n8k8.row.col.f32.tf32.tf32.f32 "
                "{%0,%1,%2,%3}, {%4,%5,%6,%7}, {%8,%9}, {%0,%1,%2,%3};\n"
                : "+f"(d0), "+f"(d1), "+f"(d2), "+f"(d3)
                : "r"(a[ks][0]), "r"(a[ks][1]), "r"(a[ks][2]), "r"(a[ks][3]),
                  "r"(bf[ks][0]), "r"(bf[ks][1]));
        }
        d0 += bias0; d1 += bias0; d2 += bias1; d3 += bias1;
        int w = warp * 32 + nt * 8 + 2 * tig;
        if (mode) {
            d0 = gelu_t(d0); d1 = gelu_t(d1);
            d2 = gelu_t(d2); d3 = gelu_t(d3);
            *(float2*)(out0 + w) = make_float2(d0, d1);
            *(float2*)(out1 + w) = make_float2(d2, d3);
        } else {
            outs[gid][w] = d0;     outs[gid][w + 1] = d1;
            outs[gid + 8][w] = d2; outs[gid + 8][w + 1] = d3;
        }
    }
    if (mode) return;
    // ---- fused proj1 + gelu + pool (mode 0) ----
    __syncthreads();
    int m_base = warp * 16;
    unsigned pa[2][4];
    float pb[2];
    {
        int r_lo = m_base + gid;
        pb[0] = pb1[r_lo];
        pb[1] = pb1[r_lo + 8];
        #pragma unroll
        for (int ks = 0; ks < 2; ks++) {
            int c_lo = ks * 8 + tig;
            pa[ks][0] = f2tf32(pw1[r_lo * 16 + c_lo]);
            pa[ks][1] = f2tf32(pw1[(r_lo + 8) * 16 + c_lo]);
            pa[ks][2] = f2tf32(pw1[r_lo * 16 + c_lo + 4]);
            pa[ks][3] = f2tf32(pw1[(r_lo + 8) * 16 + c_lo + 4]);
        }
    }
    float s0 = 0.f, s1 = 0.f;
    #pragma unroll
    for (int nt = 0; nt < 32; nt++) {
        int n = nt * 8 + gid;
        unsigned bfr[2][2];
        bfr[0][0] = f2tf32(outs[tig][n]);
        bfr[0][1] = f2tf32(outs[tig + 4][n]);
        bfr[1][0] = f2tf32(outs[8 + tig][n]);
        bfr[1][1] = f2tf32(outs[12 + tig][n]);
        float d0 = 0.f, d1 = 0.f, d2 = 0.f, d3 = 0.f;
        #pragma unroll
        for (int ks = 0; ks < 2; ks++) {
            asm volatile(
                "mma.sync.aligned.m16n8k8.row.col.f32.tf32.tf32.f32 "
                "{%0,%1,%2,%3}, {%4,%5,%6,%7}, {%8,%9}, {%0,%1,%2,%3};\n"
                : "+f"(d0), "+f"(d1), "+f"(d2), "+f"(d3)
                : "r"(pa[ks][0]), "r"(pa[ks][1]), "r"(pa[ks][2]), "r"(pa[ks][3]),
                  "r"(bfr[ks][0]), "r"(bfr[ks][1]));
        }
        s0 += gelu_t(d0 + pb[0]) + gelu_t(d1 + pb[0]);
        s1 += gelu_t(d2 + pb[1]) + gelu_t(d3 + pb[1]);
    }
    s0 += __shfl_xor_sync(0xFFFFFFFFu, s0, 1);
    s0 += __shfl_xor_sync(0xFFFFFFFFu, s0, 2);
    s1 += __shfl_xor_sync(0xFFFFFFFFu, s1, 1);
    s1 += __shfl_xor_sync(0xFFFFFFFFu, s1, 2);
    if (tig == 0) {
        float* dst = g_pool + (size_t)(b * 256 + h) * 128;
        dst[m_base + gid] = s0;
        dst[m_base + gid + 8] = s1;
    }
}

// ---------------- final reduce + proj2 on pooled vector + head -----------
__global__ void k_head(const float* __restrict__ w2, const float* __restrict__ b2,
                       const float* __restrict__ hw_, const float* __restrict__ hb,
                       float* __restrict__ out) {
    __shared__ float pq[128];
    __shared__ float f[64];
    int b = blockIdx.x, t = threadIdx.x;
    float s = 0.f;
    for (int k = 0; k < 256; k++)
        s += g_pool[((size_t)(b * 256 + k)) * 128 + t];
    pq[t] = s * (1.0f / 65536.0f);
    __syncthreads();
    if (t < 64) {
        float a = b2[t];
        #pragma unroll 8
        for (int i = 0; i < 128; i++) a += w2[t * 128 + i] * pq[i];
        f[t] = a;
    }
    __syncthreads();
    if (t < 2) {
        float a = hb[t];
        #pragma unroll
        for (int o = 0; o < 64; o++) a += hw_[t * 64 + o] * f[o];
        float e = __expf(2.0f * a);
        out[b * 2 + t] = 1.0f - 2.0f / (e + 1.0f);
    }
}

extern "C" void kernel_launch(void* const* d_in, const int* in_sizes, int n_in,
                              void* d_out, int out_size) {
    const float* x    = (const float*)d_in[0];
    const float* lw   = (const float*)d_in[1];
    const float* lb   = (const float*)d_in[2];
    const float* w1r  = (const float*)d_in[3];
    const float* w1i  = (const float*)d_in[4];
    const float* w2r  = (const float*)d_in[5];
    const float* w2i  = (const float*)d_in[6];
    const float* skw  = (const float*)d_in[7];
    const float* skb  = (const float*)d_in[8];
    const float* pw1  = (const float*)d_in[9];
    const float* pb1  = (const float*)d_in[10];
    const float* pw2  = (const float*)d_in[11];
    const float* pb2  = (const float*)d_in[12];
    const float* hw_  = (const float*)d_in[13];
    const float* hb   = (const float*)d_in[14];
    float* out = (float*)d_out;

    k_tw<<<448, 256>>>();
    k_lift<<<BCHW / 256, 256>>>(x, lw, lb);
    for (int l = 0; l < Ln; l++) {
        int flip = l & 1;                    // input buffer: 0 -> g_v0
        k_xdft  <<<1024, 128>>>(flip);
        k_ydft  <<<512, 128>>>();
        k_mix   <<<512, 256>>>(w1r, w1i, w2r, w2i, l);
        k_hsynth<<<256, 256>>>();
        k_wsynth<<<4096, 256>>>(skw, skb, pw1, pb1, l,
                                (l < Ln - 1) ? 1 : 0, flip);
    }
    k_head<<<Bn, 128>>>(pw2, pb2, hw_, hb, out);
}

// round 14
// speedup vs baseline: 2.1809x; 1.0543x over previous
#include <cuda_runtime.h>

// FNO with global head. B=16, C=16, H=W=256, L=4, modes 16x16.
// R14: R13 base (557us) + lift eliminated via rank-1 layer-0 factorization
//      (xdft0 on x + per-channel expand; wsynth l0 builds skip from x) +
//      ydft K-split 4->8 (grid 1024, same total staging).

#define Bn 16
#define Cn 16
#define Hn 256
#define Wn 256
#define Ln 4
#define BCHW (Bn*Cn*Hn*Wn)
#define PP (Bn*Cn*1024)

__device__ float g_v0[BCHW];                 // ping
__device__ float g_v1[BCHW];                 // pong
__device__ float g_a  [Bn*Cn*Hn*32];         // x-DFT result [row][2kx+ri]
__device__ float g_a0 [Bn*Hn*32];            // layer-0 x-DFT of raw x
__device__ float g_vftp[8*PP];               // ydft partials [ks][bc][...]
__device__ float g_mix[Bn*Cn*32*32];         // after channel mix
__device__ float g_gs [Bn*Cn*Hn*32];         // h-synth [bc*256+h][kx*2+ri]
__device__ float g_ehi[256*32];              // xdft E hi (tf32-rounded)
__device__ float g_elo[256*32];              // xdft E lo (residual)
__device__ float g_xc[16*256];               // wsynth cos[kx][w]
__device__ float g_xs[16*256];               // wsynth sin[kx][w]
__device__ float g_Thi[64*512];              // ydft T hi: [2m+ri][2h+p]
__device__ float g_Tlo[64*512];              // ydft T lo (residual)
__device__ float g_E3[512*64];               // hsynth E3: [2h+ro][2m+p]
__device__ float g_pool[Bn*256*128];         // proj partial sums (per b,h)

__device__ __forceinline__ float gelu_t(float x) {
    const float k0 = 0.7978845608028654f;
    const float k1 = 0.044715f;
    float y = k0 * x * (1.0f + k1 * x * x);
    float th;
    asm("tanh.approx.f32 %0, %1;" : "=f"(th) : "f"(y));
    return 0.5f * x * (1.0f + th);
}

__device__ __forceinline__ unsigned f2tf32(float f) {
    unsigned u;
    asm("cvt.rna.tf32.f32 %0, %1;" : "=r"(u) : "f"(f));
    return u;
}

#define MMA_TF32(D, A, B0, B1)                                            \
    asm volatile(                                                          \
        "mma.sync.aligned.m16n8k8.row.col.f32.tf32.tf32.f32 "             \
        "{%0,%1,%2,%3}, {%4,%5,%6,%7}, {%8,%9}, {%0,%1,%2,%3};\n"         \
        : "+f"(D[0]), "+f"(D[1]), "+f"(D[2]), "+f"(D[3])                   \
        : "r"(A[0]), "r"(A[1]), "r"(A[2]), "r"(A[3]), "r"(B0), "r"(B1))

// ---------------- build all constant tables (grid 448) ----------------
__global__ void k_tw() {
    int j = blockIdx.x * 256 + threadIdx.x;
    if (j < 8192) {                                   // g_ehi / g_elo
        int w = j >> 5, c = j & 31;
        int kx = c >> 1, ri = c & 1;
        float ang = (float)((kx * w) & 255) / 128.0f;
        float e = ri ? -sinpif(ang) : cospif(ang);
        float hi = __uint_as_float(f2tf32(e));
        g_ehi[j] = hi;
        g_elo[j] = __uint_as_float(f2tf32(e - hi));
    } else if (j < 12288) {                           // g_xc
        int e = j - 8192;
        int kx = e >> 8, w = e & 255;
        g_xc[e] = cospif((float)((kx * w) & 255) / 128.0f);
    } else if (j < 16384) {                           // g_xs
        int e = j - 12288;
        int kx = e >> 8, w = e & 255;
        g_xs[e] = sinpif((float)((kx * w) & 255) / 128.0f);
    } else if (j < 49152) {                           // g_Thi [2m+ri][2h+p]
        int e = j - 16384;
        int row = e >> 9, col = e & 511;
        int m = row >> 1, ri = row & 1;
        int h = col >> 1, p = col & 1;
        int ky = (m < 16) ? m : (m + 224);
        float ang = (float)((ky * h) & 255) / 128.0f;
        float cy = cospif(ang), sy = sinpif(ang);
        float v = (ri == 0) ? (p == 0 ? cy : sy) : (p == 0 ? -sy : cy);
        g_Thi[e] = __uint_as_float(f2tf32(v));
    } else if (j < 81920) {                           // g_E3 [2h+ro][2m+p]
        int e = j - 49152;
        int row = e >> 6, col = e & 63;
        int h = row >> 1, ro = row & 1;
        int m = col >> 1, p = col & 1;
        int ky = (m < 16) ? m : (m + 224);
        float ang = (float)((ky * h) & 255) / 128.0f;
        float cy = cospif(ang), sy = sinpif(ang);
        g_E3[e] = (ro == 0) ? (p == 0 ? cy : -sy) : (p == 0 ? sy : cy);
    } else if (j < 114688) {                          // g_Tlo
        int e = j - 81920;
        int row = e >> 9, col = e & 511;
        int m = row >> 1, ri = row & 1;
        int h = col >> 1, p = col & 1;
        int ky = (m < 16) ? m : (m + 224);
        float ang = (float)((ky * h) & 255) / 128.0f;
        float cy = cospif(ang), sy = sinpif(ang);
        float v = (ri == 0) ? (p == 0 ? cy : sy) : (p == 0 ? -sy : cy);
        float hi = __uint_as_float(f2tf32(v));
        g_Tlo[e] = __uint_as_float(f2tf32(v - hi));
    }
}

// ---------------- generic x-DFT body (3xTF32), src rows -> dst -----------
__device__ __forceinline__ void xdft_body(const float* __restrict__ src,
                                          float* __restrict__ dst,
                                          int rowbase) {
    __shared__ float vs[64][68];
    __shared__ float eh[64][40];
    __shared__ float el[64][40];
    int t = threadIdx.x;
    int lane = t & 31, warp = t >> 5;
    int gid = lane >> 2, tig = lane & 3;
    const float* s = src + (size_t)rowbase * 256;
    float d[4][4] = {};
    for (int kc = 0; kc < 4; kc++) {
        __syncthreads();
        for (int j = t; j < 1024; j += 128) {
            int r = j >> 4, q = j & 15;
            float4 v4 = *(const float4*)(s + r * 256 + kc * 64 + q * 4);
            vs[r][q * 4 + 0] = v4.x; vs[r][q * 4 + 1] = v4.y;
            vs[r][q * 4 + 2] = v4.z; vs[r][q * 4 + 3] = v4.w;
        }
        for (int j = t; j < 512; j += 128) {
            int k = j >> 3, q = j & 7;
            float4 h4 = *(const float4*)(g_ehi + (size_t)(kc * 64 + k) * 32 + q * 4);
            eh[k][q * 4 + 0] = h4.x; eh[k][q * 4 + 1] = h4.y;
            eh[k][q * 4 + 2] = h4.z; eh[k][q * 4 + 3] = h4.w;
            float4 l4 = *(const float4*)(g_elo + (size_t)(kc * 64 + k) * 32 + q * 4);
            el[k][q * 4 + 0] = l4.x; el[k][q * 4 + 1] = l4.y;
            el[k][q * 4 + 2] = l4.z; el[k][q * 4 + 3] = l4.w;
        }
        __syncthreads();
        #pragma unroll
        for (int ks = 0; ks < 8; ks++) {
            int kk = ks * 8;
            int m0 = warp * 16 + gid;
            float va[4];
            va[0] = vs[m0][kk + tig];     va[1] = vs[m0 + 8][kk + tig];
            va[2] = vs[m0][kk + tig + 4]; va[3] = vs[m0 + 8][kk + tig + 4];
            unsigned ah[4], al_[4];
            #pragma unroll
            for (int i = 0; i < 4; i++) {
                ah[i] = f2tf32(va[i]);
                al_[i] = f2tf32(va[i] - __uint_as_float(ah[i]));
            }
            #pragma unroll
            for (int nt = 0; nt < 4; nt++) {
                int n = nt * 8 + gid;
                unsigned bh0 = __float_as_uint(eh[kk + tig][n]);
                unsigned bh1 = __float_as_uint(eh[kk + tig + 4][n]);
                unsigned bl0 = __float_as_uint(el[kk + tig][n]);
                unsigned bl1 = __float_as_uint(el[kk + tig + 4][n]);
                MMA_TF32(d[nt], ah, bh0, bh1);
                MMA_TF32(d[nt], al_, bh0, bh1);
                MMA_TF32(d[nt], ah, bl0, bl1);
            }
        }
    }
    int m0 = rowbase + warp * 16 + gid;
    #pragma unroll
    for (int nt = 0; nt < 4; nt++) {
        int c0 = nt * 8 + 2 * tig;
        *(float2*)(dst + (size_t)m0 * 32 + c0) = make_float2(d[nt][0], d[nt][1]);
        *(float2*)(dst + (size_t)(m0 + 8) * 32 + c0) = make_float2(d[nt][2], d[nt][3]);
    }
}

__global__ void __launch_bounds__(128) k_xdft(int flip) {
    xdft_body(flip ? g_v1 : g_v0, g_a, blockIdx.x * 64);
}

// layer-0: DFT of raw x, 4096 rows (grid 64)
__global__ void __launch_bounds__(128) k_xdft0(const float* __restrict__ x) {
    xdft_body(x, g_a0, blockIdx.x * 64);
}

// expand: g_a[b,c,h,:] = lw[c]*g_a0[b,h,:] + 256*lb[c]*delta(idx==0)
__global__ void __launch_bounds__(256) k_expand(const float* __restrict__ lw,
                                                const float* __restrict__ lb) {
    int j = blockIdx.x * 256 + threadIdx.x;   // 524288 float4 groups
    int c2 = (j * 4) & 31;
    int h = (j >> 3) & 255;
    int c = (j >> 11) & 15;
    int b = j >> 15;
    float4 v = *(const float4*)(g_a0 + (size_t)((b * 256 + h) * 32) + c2);
    float s = lw[c];
    v.x *= s; v.y *= s; v.z *= s; v.w *= s;
    if (c2 == 0) v.x += 256.0f * lb[c];
    *(float4*)(g_a + (size_t)(((b * 16 + c) * 256 + h) * 32) + c2) = v;
}

// ---------------- y-DFT via 3xTF32 mma, K-split x8 ------------------------
// grid 1024 = (bc/2)*8; block: one 64-k chunk of C_part[64,32].
__global__ void __launch_bounds__(128) k_ydft() {
    __shared__ float th[64][68];      // Thi chunk [row][k]
    __shared__ float tl[64][68];      // Tlo chunk
    __shared__ float as[64][36];      // A chunk [k][col=bcq*16+kx]
    int t = threadIdx.x;
    int lane = t & 31, warp = t >> 5;
    int gid = lane >> 2, tig = lane & 3;
    int ks8 = blockIdx.x & 7;
    int bc0 = (blockIdx.x >> 3) * 2;
    float d[4][4] = {};
    int h0 = ks8 * 32, k0 = ks8 * 64;
    for (int j = t; j < 1024; j += 128) {
        int row = j >> 4, q = j & 15;
        float4 h4 = *(const float4*)(g_Thi + (size_t)row * 512 + k0 + q * 4);
        th[row][q * 4 + 0] = h4.x; th[row][q * 4 + 1] = h4.y;
        th[row][q * 4 + 2] = h4.z; th[row][q * 4 + 3] = h4.w;
        float4 l4 = *(const float4*)(g_Tlo + (size_t)row * 512 + k0 + q * 4);
        tl[row][q * 4 + 0] = l4.x; tl[row][q * 4 + 1] = l4.y;
        tl[row][q * 4 + 2] = l4.z; tl[row][q * 4 + 3] = l4.w;
    }
    for (int j = t; j < 512; j += 128) {
        int bcq = j >> 8, rem = j & 255, hh = rem >> 3, q = rem & 7;
        float4 v4 = *(const float4*)(g_a + (size_t)((bc0 + bcq) * 256 + h0 + hh) * 32 + q * 4);
        int n0 = bcq * 16 + q * 2;
        as[2 * hh + 0][n0] = v4.x;     as[2 * hh + 1][n0] = v4.y;
        as[2 * hh + 0][n0 + 1] = v4.z; as[2 * hh + 1][n0 + 1] = v4.w;
    }
    __syncthreads();
    #pragma unroll
    for (int ks = 0; ks < 8; ks++) {
        int kk = ks * 8;
        int m0 = warp * 16 + gid;
        unsigned ah[4], al_[4];
        ah[0] = __float_as_uint(th[m0][kk + tig]);
        ah[1] = __float_as_uint(th[m0 + 8][kk + tig]);
        ah[2] = __float_as_uint(th[m0][kk + tig + 4]);
        ah[3] = __float_as_uint(th[m0 + 8][kk + tig + 4]);
        al_[0] = __float_as_uint(tl[m0][kk + tig]);
        al_[1] = __float_as_uint(tl[m0 + 8][kk + tig]);
        al_[2] = __float_as_uint(tl[m0][kk + tig + 4]);
        al_[3] = __float_as_uint(tl[m0 + 8][kk + tig + 4]);
        #pragma unroll
        for (int nt = 0; nt < 4; nt++) {
            int n = nt * 8 + gid;
            float b0 = as[kk + tig][n];
            float b1 = as[kk + tig + 4][n];
            unsigned bh0 = f2tf32(b0);
            unsigned bh1 = f2tf32(b1);
            unsigned bl0 = f2tf32(b0 - __uint_as_float(bh0));
            unsigned bl1 = f2tf32(b1 - __uint_as_float(bh1));
            MMA_TF32(d[nt], ah, bh0, bh1);
            MMA_TF32(d[nt], al_, bh0, bh1);
            MMA_TF32(d[nt], ah, bl0, bl1);
        }
    }
    float* vout = g_vftp + (size_t)ks8 * PP;
    #pragma unroll
    for (int nt = 0; nt < 4; nt++) {
        #pragma unroll
        for (int e = 0; e < 4; e++) {
            int r = warp * 16 + gid + (e >= 2 ? 8 : 0);
            int c = nt * 8 + 2 * tig + (e & 1);
            int m = r >> 1, ri = r & 1;
            int bcq = c >> 4, kx = c & 15;
            vout[(bc0 + bcq) * 1024 + m * 32 + kx * 2 + ri] = d[nt][e];
        }
    }
}

// ---------------- per-mode 16x16 complex channel mixing (sums 8 partials)
__global__ void k_mix(const float* __restrict__ w1r, const float* __restrict__ w1i,
                      const float* __restrict__ w2r, const float* __restrict__ w2i,
                      int l) {
    int tid = blockIdx.x * blockDim.x + threadIdx.x;   // 131072
    int kx = tid & 15;
    int m = (tid >> 4) & 31;
    int o = (tid >> 9) & 15;
    int b = tid >> 13;
    int mm = m & 15;
    const float* wr = (m < 16) ? w1r : w2r;
    const float* wi = (m < 16) ? w1i : w2i;
    float accr = 0.f, acci = 0.f;
    #pragma unroll
    for (int i = 0; i < 16; i++) {
        int vidx = (b * 16 + i) * 1024 + m * 32 + kx * 2;
        float vr = 0.f, vv = 0.f;
        #pragma unroll
        for (int p = 0; p < 8; p++) {
            float2 pv = *(const float2*)(g_vftp + (size_t)p * PP + vidx);
            vr += pv.x; vv += pv.y;
        }
        int widx = (((l * 16 + i) * 16 + o) * 256) + mm * 16 + kx;
        float wrv = wr[widx], wiv = wi[widx];
        accr += vr * wrv - vv * wiv;
        acci += vr * wiv + vv * wrv;
    }
    int outi = (b * 16 + o) * 1024 + m * 32 + kx * 2;
    g_mix[outi + 0] = accr;
    g_mix[outi + 1] = acci;
}

// ---------------- h-synthesis GEMM per bc: C[512,16] = E3[512,64] x M ----
__global__ void __launch_bounds__(256) k_hsynth() {
    __shared__ float mixT[16][68];    // [kx][2m+p]
    int t = threadIdx.x;
    int bc = blockIdx.x;
    {
        float4 v4 = *(const float4*)(g_mix + (size_t)bc * 1024 + t * 4);
        int i4 = t * 4;
        #pragma unroll
        for (int e = 0; e < 4; e++) {
            int idx = i4 + e;
            int m = idx >> 5, rem = idx & 31, kx = rem >> 1, p = rem & 1;
            float val = (e == 0) ? v4.x : (e == 1) ? v4.y : (e == 2) ? v4.z : v4.w;
            mixT[kx][2 * m + p] = val;
        }
    }
    __syncthreads();
    int rg = t >> 3, cg = t & 7;
    float acc[16][2] = {};
    for (int ks = 0; ks < 64; ks += 4) {
        float4 bf0 = *(const float4*)&mixT[cg * 2 + 0][ks];
        float4 bf1 = *(const float4*)&mixT[cg * 2 + 1][ks];
        #pragma unroll
        for (int i = 0; i < 16; i++) {
            float4 af = *(const float4*)(g_E3 + (size_t)(32 * i + rg) * 64 + ks);
            acc[i][0] += af.x * bf0.x + af.y * bf0.y + af.z * bf0.z + af.w * bf0.w;
            acc[i][1] += af.x * bf1.x + af.y * bf1.y + af.z * bf1.z + af.w * bf1.w;
        }
    }
    #pragma unroll
    for (int i = 0; i < 16; i++) {
        int r = 32 * i + rg, h = r >> 1, ro = r & 1;
        #pragma unroll
        for (int jj = 0; jj < 2; jj++) {
            int kx = cg * 2 + jj;
            float sc = (kx == 0) ? (1.0f / 65536.0f) : (2.0f / 65536.0f);
            g_gs[(size_t)(bc * 256 + h) * 32 + kx * 2 + ro] = acc[i][jj] * sc;
        }
    }
}

// ---------------- fused w-synth + skip (+ gelu | + proj1+gelu+pool) ------
// first=1: build skip tile from raw x via lift (v = lw[c]*x + lb[c]).
__global__ void __launch_bounds__(256) k_wsynth(const float* __restrict__ skw,
                         const float* __restrict__ skb,
                         const float* __restrict__ pw1,
                         const float* __restrict__ pb1,
                         const float* __restrict__ x,
                         const float* __restrict__ lw,
                         const float* __restrict__ lb,
                         int l, int mode, int first, int flip) {
    __shared__ float vs[16][260];
    __shared__ float ms[16][52];      // [o][0:16 skw | 16:32 gr | 32:48 -gi]
    __shared__ float sb[16];
    __shared__ float outs[16][264];   // staged OUT for fused proj (mode 0)
    const float* __restrict__ vin = flip ? g_v1 : g_v0;
    float* __restrict__ vout = flip ? g_v0 : g_v1;
    int t = threadIdx.x;
    int lane = t & 31, warp = t >> 5;
    int b = blockIdx.x >> 8, h = blockIdx.x & 255;
    if (first) {
        const float* xrow = x + ((size_t)b * 256 + h) * 256;
        for (int j = t; j < 1024; j += 256) {
            int c = j >> 6, q = j & 63;
            float4 v4 = *(const float4*)(xrow + q * 4);
            float s = lw[c], o = lb[c];
            vs[c][q * 4 + 0] = s * v4.x + o; vs[c][q * 4 + 1] = s * v4.y + o;
            vs[c][q * 4 + 2] = s * v4.z + o; vs[c][q * 4 + 3] = s * v4.w + o;
        }
    } else {
        for (int j = t; j < 1024; j += 256) {
            int c = j >> 6, q = j & 63;
            float4 v4 = *(const float4*)(vin + ((size_t)(b * 16 + c) * 256 + h) * 256 + q * 4);
            vs[c][q * 4 + 0] = v4.x; vs[c][q * 4 + 1] = v4.y;
            vs[c][q * 4 + 2] = v4.z; vs[c][q * 4 + 3] = v4.w;
        }
    }
    {
        int c = t >> 4, k = t & 15;
        ms[c][k] = skw[l * 256 + c * 16 + k];
        int base = ((size_t)(b * 16 + c) * 256 + h) * 32 + k * 2;
        ms[c][16 + k] = g_gs[base];
        ms[c][32 + k] = -g_gs[base + 1];
        if (t < 16) sb[t] = skb[l * 16 + t];
    }
    __syncthreads();
    int gid = lane >> 2, tig = lane & 3;
    unsigned a[6][4];
    #pragma unroll
    for (int ks = 0; ks < 6; ks++) {
        int c0 = ks * 8 + tig;
        a[ks][0] = f2tf32(ms[gid][c0]);
        a[ks][1] = f2tf32(ms[gid + 8][c0]);
        a[ks][2] = f2tf32(ms[gid][c0 + 4]);
        a[ks][3] = f2tf32(ms[gid + 8][c0 + 4]);
    }
    float bias0 = sb[gid], bias1 = sb[gid + 8];
    float* out0 = vout + ((size_t)(b * 16 + gid) * 256 + h) * 256;
    float* out1 = vout + ((size_t)(b * 16 + gid + 8) * 256 + h) * 256;
    #pragma unroll
    for (int nt = 0; nt < 4; nt++) {
        int n = warp * 32 + nt * 8 + gid;
        unsigned bf[6][2];
        bf[0][0] = f2tf32(vs[tig][n]);        bf[0][1] = f2tf32(vs[tig + 4][n]);
        bf[1][0] = f2tf32(vs[8 + tig][n]);    bf[1][1] = f2tf32(vs[12 + tig][n]);
        bf[2][0] = f2tf32(g_xc[tig * 256 + n]);
        bf[2][1] = f2tf32(g_xc[(tig + 4) * 256 + n]);
        bf[3][0] = f2tf32(g_xc[(8 + tig) * 256 + n]);
        bf[3][1] = f2tf32(g_xc[(12 + tig) * 256 + n]);
        bf[4][0] = f2tf32(g_xs[tig * 256 + n]);
        bf[4][1] = f2tf32(g_xs[(tig + 4) * 256 + n]);
        bf[5][0] = f2tf32(g_xs[(8 + tig) * 256 + n]);
        bf[5][1] = f2tf32(g_xs[(12 + tig) * 256 + n]);
        float d0 = 0.f, d1 = 0.f, d2 = 0.f, d3 = 0.f;
        #pragma unroll
        for (int ks = 0; ks < 6; ks++) {
            asm volatile(
                "mma.sync.aligned.m16n8k8.row.col.f32.tf32.tf32.f32 "
                "{%0,%1,%2,%3}, {%4,%5,%6,%7}, {%8,%9}, {%0,%1,%2,%3};\n"
                : "+f"(d0), "+f"(d1), "+f"(d2), "+f"(d3)
                : "r"(a[ks][0]), "r"(a[ks][1]), "r"(a[ks][2]), "r"(a[ks][3]),
                  "r"(bf[ks][0]), "r"(bf[ks][1]));
        }
        d0 += bias0; d1 += bias0; d2 += bias1; d3 += bias1;
        int w = warp * 32 + nt * 8 + 2 * tig;
        if (mode) {
            d0 = gelu_t(d0); d1 = gelu_t(d1);
            d2 = gelu_t(d2); d3 = gelu_t(d3);
            *(float2*)(out0 + w) = make_float2(d0, d1);
            *(float2*)(out1 + w) = make_float2(d2, d3);
        } else {
            outs[gid][w] = d0;     outs[gid][w + 1] = d1;
            outs[gid + 8][w] = d2; outs[gid + 8][w + 1] = d3;
        }
    }
    if (mode) return;
    // ---- fused proj1 + gelu + pool (mode 0) ----
    __syncthreads();
    int m_base = warp * 16;
    unsigned pa[2][4];
    float pb[2];
    {
        int r_lo = m_base + gid;
        pb[0] = pb1[r_lo];
        pb[1] = pb1[r_lo + 8];
        #pragma unroll
        for (int ks = 0; ks < 2; ks++) {
            int c_lo = ks * 8 + tig;
            pa[ks][0] = f2tf32(pw1[r_lo * 16 + c_lo]);
            pa[ks][1] = f2tf32(pw1[(r_lo + 8) * 16 + c_lo]);
            pa[ks][2] = f2tf32(pw1[r_lo * 16 + c_lo + 4]);
            pa[ks][3] = f2tf32(pw1[(r_lo + 8) * 16 + c_lo + 4]);
        }
    }
    float s0 = 0.f, s1 = 0.f;
    #pragma unroll
    for (int nt = 0; nt < 32; nt++) {
        int n = nt * 8 + gid;
        unsigned bfr[2][2];
        bfr[0][0] = f2tf32(outs[tig][n]);
        bfr[0][1] = f2tf32(outs[tig + 4][n]);
        bfr[1][0] = f2tf32(outs[8 + tig][n]);
        bfr[1][1] = f2tf32(outs[12 + tig][n]);
        float d0 = 0.f, d1 = 0.f, d2 = 0.f, d3 = 0.f;
        #pragma unroll
        for (int ks = 0; ks < 2; ks++) {
            asm volatile(
                "mma.sync.aligned.m16n8k8.row.col.f32.tf32.tf32.f32 "
                "{%0,%1,%2,%3}, {%4,%5,%6,%7}, {%8,%9}, {%0,%1,%2,%3};\n"
                : "+f"(d0), "+f"(d1), "+f"(d2), "+f"(d3)
                : "r"(pa[ks][0]), "r"(pa[ks][1]), "r"(pa[ks][2]), "r"(pa[ks][3]),
                  "r"(bfr[ks][0]), "r"(bfr[ks][1]));
        }
        s0 += gelu_t(d0 + pb[0]) + gelu_t(d1 + pb[0]);
        s1 += gelu_t(d2 + pb[1]) + gelu_t(d3 + pb[1]);
    }
    s0 += __shfl_xor_sync(0xFFFFFFFFu, s0, 1);
    s0 += __shfl_xor_sync(0xFFFFFFFFu, s0, 2);
    s1 += __shfl_xor_sync(0xFFFFFFFFu, s1, 1);
    s1 += __shfl_xor_sync(0xFFFFFFFFu, s1, 2);
    if (tig == 0) {
        float* dst = g_pool + (size_t)(b * 256 + h) * 128;
        dst[m_base + gid] = s0;
        dst[m_base + gid + 8] = s1;
    }
}

// ---------------- final reduce + proj2 on pooled vector + head -----------
__global__ void k_head(const float* __restrict__ w2, const float* __restrict__ b2,
                       const float* __restrict__ hw_, const float* __restrict__ hb,
                       float* __restrict__ out) {
    __shared__ float pq[128];
    __shared__ float f[64];
    int b = blockIdx.x, t = threadIdx.x;
    float s = 0.f;
    for (int k = 0; k < 256; k++)
        s += g_pool[((size_t)(b * 256 + k)) * 128 + t];
    pq[t] = s * (1.0f / 65536.0f);
    __syncthreads();
    if (t < 64) {
        float a = b2[t];
        #pragma unroll 8
        for (int i = 0; i < 128; i++) a += w2[t * 128 + i] * pq[i];
        f[t] = a;
    }
    __syncthreads();
    if (t < 2) {
        float a = hb[t];
        #pragma unroll
        for (int o = 0; o < 64; o++) a += hw_[t * 64 + o] * f[o];
        float e = __expf(2.0f * a);
        out[b * 2 + t] = 1.0f - 2.0f / (e + 1.0f);
    }
}

extern "C" void kernel_launch(void* const* d_in, const int* in_sizes, int n_in,
                              void* d_out, int out_size) {
    const float* x    = (const float*)d_in[0];
    const float* lw   = (const float*)d_in[1];
    const float* lb   = (const float*)d_in[2];
    const float* w1r  = (const float*)d_in[3];
    const float* w1i  = (const float*)d_in[4];
    const float* w2r  = (const float*)d_in[5];
    const float* w2i  = (const float*)d_in[6];
    const float* skw  = (const float*)d_in[7];
    const float* skb  = (const float*)d_in[8];
    const float* pw1  = (const float*)d_in[9];
    const float* pb1  = (const float*)d_in[10];
    const float* pw2  = (const float*)d_in[11];
    const float* pb2  = (const float*)d_in[12];
    const float* hw_  = (const float*)d_in[13];
    const float* hb   = (const float*)d_in[14];
    float* out = (float*)d_out;

    k_tw<<<448, 256>>>();
    for (int l = 0; l < Ln; l++) {
        int flip = l & 1;                    // buffers: wsynth l writes flip?v0:v1
        if (l == 0) {
            k_xdft0 <<<64, 128>>>(x);
            k_expand<<<2048, 256>>>(lw, lb);
        } else {
            k_xdft  <<<1024, 128>>>(flip);
        }
        k_ydft  <<<1024, 128>>>();
        k_mix   <<<512, 256>>>(w1r, w1i, w2r, w2i, l);
        k_hsynth<<<256, 256>>>();
        k_wsynth<<<4096, 256>>>(skw, skb, pw1, pb1, x, lw, lb, l,
                                (l < Ln - 1) ? 1 : 0, (l == 0) ? 1 : 0, flip);
    }
    k_head<<<Bn, 128>>>(pw2, pb2, hw_, hb, out);
}